// round 1
// baseline (speedup 1.0000x reference)
#include <cuda_runtime.h>
#include <math_constants.h>
#include <stdint.h>

// Problem constants (max sizes for static scratch; actual sizes derived from in_sizes)
#define MAXN 100000
#define MAXE 1600000
#define F 128
#define F4 32            // F/4
#define NCLS 40

// ---------------- device scratch (no allocations allowed) ----------------
__device__ int   g_is64;
__device__ int   g_src[MAXE];
__device__ int   g_dst[MAXE];
__device__ int   g_perm_src[MAXE];
__device__ float g_perm_ea[MAXE];
__device__ int   g_counts[MAXN + 1];
__device__ int   g_offsets[MAXN + 1];
__device__ int   g_cursor[MAXN];
__device__ float g_buf_a[(size_t)MAXN * F];
__device__ float g_buf_b[(size_t)MAXN * F];

// ---------------- dtype detection: int64 vs int32 edge_index ----------------
__global__ void detect_kernel(const unsigned int* __restrict__ ei) {
    __shared__ int any_nonzero;
    if (threadIdx.x == 0) any_nonzero = 0;
    __syncthreads();
    // If int64 (little-endian, values < 2^31), every odd 32-bit word is 0.
    for (int i = threadIdx.x; i < 1024; i += blockDim.x) {
        if (ei[2 * i + 1] != 0u) any_nonzero = 1;
    }
    __syncthreads();
    if (threadIdx.x == 0) g_is64 = (any_nonzero == 0) ? 1 : 0;
}

__global__ void extract_kernel(const void* __restrict__ ei, int E) {
    int e = blockIdx.x * blockDim.x + threadIdx.x;
    if (e >= E) return;
    if (g_is64) {
        const long long* p = (const long long*)ei;
        g_src[e] = (int)p[e];
        g_dst[e] = (int)p[(size_t)E + e];
    } else {
        const int* p = (const int*)ei;
        g_src[e] = p[e];
        g_dst[e] = p[E + e];
    }
}

// ---------------- CSR build ----------------
__global__ void zero_counts_kernel(int n) {
    int i = blockIdx.x * blockDim.x + threadIdx.x;
    if (i <= n) g_counts[i] = 0;
}

__global__ void hist_kernel(int E) {
    int e = blockIdx.x * blockDim.x + threadIdx.x;
    if (e >= E) return;
    atomicAdd(&g_counts[g_dst[e]], 1);
}

// Single-block scan over N counts -> exclusive offsets (+ cursor copy)
__global__ void scan_kernel(int n) {
    __shared__ int sums[1024];
    int t = threadIdx.x;
    int CH = (n + 1023) / 1024;
    int start = t * CH; if (start > n) start = n;
    int end = start + CH; if (end > n) end = n;
    int s = 0;
    for (int i = start; i < end; i++) s += g_counts[i];
    sums[t] = s;
    __syncthreads();
    // inclusive scan (Hillis-Steele)
    for (int off = 1; off < 1024; off <<= 1) {
        int v = 0;
        if (t >= off) v = sums[t - off];
        __syncthreads();
        sums[t] += v;
        __syncthreads();
    }
    int excl = sums[t] - s;   // sum of all previous chunks
    int run = excl;
    for (int i = start; i < end; i++) {
        g_offsets[i] = run;
        g_cursor[i]  = run;
        run += g_counts[i];
    }
    if (t == 0) g_offsets[n] = sums[1023];
}

__global__ void scatter_kernel(const float* __restrict__ edge_attr, int E) {
    int e = blockIdx.x * blockDim.x + threadIdx.x;
    if (e >= E) return;
    int d = g_dst[e];
    int pos = atomicAdd(&g_cursor[d], 1);
    g_perm_src[pos] = g_src[e];
    g_perm_ea[pos]  = edge_attr[e];
}

// ---------------- GINE aggregation: warp per node, no float atomics ----------------
// out[i] = (1+eps)*in[i] + sum_{e in CSR[i]} relu(in[src_e] + ea_e * We + be)
__global__ void __launch_bounds__(256) agg_kernel(
    const float4* __restrict__ xin, const float* __restrict__ We,
    const float* __restrict__ be, const float* __restrict__ eps_p,
    float4* __restrict__ out, int n)
{
    int warp = (blockIdx.x * blockDim.x + threadIdx.x) >> 5;
    int lane = threadIdx.x & 31;
    if (warp >= n) return;

    float4 w  = ((const float4*)We)[lane];
    float4 bb = ((const float4*)be)[lane];
    int beg = g_offsets[warp];
    int end = g_offsets[warp + 1];

    float4 acc = make_float4(0.f, 0.f, 0.f, 0.f);
    for (int p = beg; p < end; p++) {
        int   s  = g_perm_src[p];
        float ea = g_perm_ea[p];
        float4 xj = __ldg(&xin[(size_t)s * F4 + lane]);
        acc.x += fmaxf(fmaf(ea, w.x, xj.x) + bb.x, 0.f);
        acc.y += fmaxf(fmaf(ea, w.y, xj.y) + bb.y, 0.f);
        acc.z += fmaxf(fmaf(ea, w.z, xj.z) + bb.z, 0.f);
        acc.w += fmaxf(fmaf(ea, w.w, xj.w) + bb.w, 0.f);
    }
    float epv = 1.f + __ldg(eps_p);
    float4 xi = __ldg(&xin[(size_t)warp * F4 + lane]);
    float4 r;
    r.x = fmaf(epv, xi.x, acc.x);
    r.y = fmaf(epv, xi.y, acc.y);
    r.z = fmaf(epv, xi.z, acc.z);
    r.w = fmaf(epv, xi.w, acc.w);
    out[(size_t)warp * F4 + lane] = r;
}

// ---------------- fused MLP: Out = relu( relu(In@W1+b1) @ W2 + b2 ) ----------------
// 128-row tile, K=N=128, 256 threads, 8x8 per-thread microtile, both GEMMs fused.
#define SLD 132   // padded smem row length
__global__ void __launch_bounds__(256) mlp_kernel(
    const float* __restrict__ In,
    const float* __restrict__ W1, const float* __restrict__ b1,
    const float* __restrict__ W2, const float* __restrict__ b2,
    float* __restrict__ Out, int n)
{
    extern __shared__ float sm[];
    float* As = sm;             // [128][SLD], stores A transposed: As[k][m]
    float* Bs = sm + 128 * SLD; // [128][SLD], Bs[k][c]

    int t  = threadIdx.x;
    int tx = t & 15;
    int ty = t >> 4;
    int m0 = blockIdx.x * 128;

    // Load In tile (transposed into As)
    #pragma unroll
    for (int r = 0; r < 16; r++) {
        int idx = t + r * 256;        // 0..4095
        int m   = idx >> 5;           // 0..127
        int k4  = (idx & 31) * 4;
        float4 v = make_float4(0.f, 0.f, 0.f, 0.f);
        if (m0 + m < n) v = *(const float4*)(In + (size_t)(m0 + m) * F + k4);
        As[(k4 + 0) * SLD + m] = v.x;
        As[(k4 + 1) * SLD + m] = v.y;
        As[(k4 + 2) * SLD + m] = v.z;
        As[(k4 + 3) * SLD + m] = v.w;
    }
    // Load W1 into Bs
    #pragma unroll
    for (int r = 0; r < 16; r++) {
        int idx = t + r * 256;
        int k   = idx >> 5;
        int c4  = (idx & 31) * 4;
        *(float4*)(Bs + k * SLD + c4) = *(const float4*)(W1 + k * F + c4);
    }
    __syncthreads();

    float acc[8][8];
    #pragma unroll
    for (int i = 0; i < 8; i++)
        #pragma unroll
        for (int j = 0; j < 8; j++) acc[i][j] = 0.f;

    #pragma unroll 4
    for (int k = 0; k < 128; k++) {
        float a[8], b[8];
        #pragma unroll
        for (int i = 0; i < 8; i++) a[i] = As[k * SLD + ty * 8 + i];
        #pragma unroll
        for (int j = 0; j < 8; j++) b[j] = Bs[k * SLD + tx * 8 + j];
        #pragma unroll
        for (int i = 0; i < 8; i++)
            #pragma unroll
            for (int j = 0; j < 8; j++) acc[i][j] = fmaf(a[i], b[j], acc[i][j]);
    }
    __syncthreads();

    // t = relu(acc + b1), write transposed back into As for stage 2
    #pragma unroll
    for (int j = 0; j < 8; j++) {
        float bj = b1[tx * 8 + j];
        #pragma unroll
        for (int i = 0; i < 8; i++) {
            float v = fmaxf(acc[i][j] + bj, 0.f);
            As[(tx * 8 + j) * SLD + ty * 8 + i] = v;
            acc[i][j] = 0.f;
        }
    }
    // Load W2 into Bs
    #pragma unroll
    for (int r = 0; r < 16; r++) {
        int idx = t + r * 256;
        int k   = idx >> 5;
        int c4  = (idx & 31) * 4;
        *(float4*)(Bs + k * SLD + c4) = *(const float4*)(W2 + k * F + c4);
    }
    __syncthreads();

    #pragma unroll 4
    for (int k = 0; k < 128; k++) {
        float a[8], b[8];
        #pragma unroll
        for (int i = 0; i < 8; i++) a[i] = As[k * SLD + ty * 8 + i];
        #pragma unroll
        for (int j = 0; j < 8; j++) b[j] = Bs[k * SLD + tx * 8 + j];
        #pragma unroll
        for (int i = 0; i < 8; i++)
            #pragma unroll
            for (int j = 0; j < 8; j++) acc[i][j] = fmaf(a[i], b[j], acc[i][j]);
    }

    // epilogue: + b2, relu, store
    #pragma unroll
    for (int i = 0; i < 8; i++) {
        int m = m0 + ty * 8 + i;
        if (m < n) {
            float4 v0, v1;
            v0.x = fmaxf(acc[i][0] + b2[tx * 8 + 0], 0.f);
            v0.y = fmaxf(acc[i][1] + b2[tx * 8 + 1], 0.f);
            v0.z = fmaxf(acc[i][2] + b2[tx * 8 + 2], 0.f);
            v0.w = fmaxf(acc[i][3] + b2[tx * 8 + 3], 0.f);
            v1.x = fmaxf(acc[i][4] + b2[tx * 8 + 4], 0.f);
            v1.y = fmaxf(acc[i][5] + b2[tx * 8 + 5], 0.f);
            v1.z = fmaxf(acc[i][6] + b2[tx * 8 + 6], 0.f);
            v1.w = fmaxf(acc[i][7] + b2[tx * 8 + 7], 0.f);
            *(float4*)(Out + (size_t)m * F + tx * 8 + 0) = v0;
            *(float4*)(Out + (size_t)m * F + tx * 8 + 4) = v1;
        }
    }
}

// ---------------- classifier + log_softmax: warp per node ----------------
__global__ void __launch_bounds__(256) cls_kernel(
    const float* __restrict__ H, const float* __restrict__ Wl,
    const float* __restrict__ bl, float* __restrict__ out, int n)
{
    int warp = (blockIdx.x * blockDim.x + threadIdx.x) >> 5;
    int lane = threadIdx.x & 31;
    if (warp >= n) return;

    int c0 = lane;                       // classes 0..31
    int c1 = (lane < 8) ? (lane + 32) : 0; // classes 32..39 on lanes 0..7
    float acc0 = bl[c0];
    float acc1 = (lane < 8) ? bl[lane + 32] : 0.f;

    const float4* H4 = (const float4*)(H + (size_t)warp * F);
    #pragma unroll 8
    for (int kk = 0; kk < 32; kk++) {
        float4 h = __ldg(&H4[kk]);
        int k = kk * 4;
        acc0 = fmaf(h.x, Wl[(k + 0) * NCLS + c0], acc0);
        acc0 = fmaf(h.y, Wl[(k + 1) * NCLS + c0], acc0);
        acc0 = fmaf(h.z, Wl[(k + 2) * NCLS + c0], acc0);
        acc0 = fmaf(h.w, Wl[(k + 3) * NCLS + c0], acc0);
        acc1 = fmaf(h.x, Wl[(k + 0) * NCLS + c1], acc1);
        acc1 = fmaf(h.y, Wl[(k + 1) * NCLS + c1], acc1);
        acc1 = fmaf(h.z, Wl[(k + 2) * NCLS + c1], acc1);
        acc1 = fmaf(h.w, Wl[(k + 3) * NCLS + c1], acc1);
    }

    float vmax = fmaxf(acc0, (lane < 8) ? acc1 : -CUDART_INF_F);
    #pragma unroll
    for (int o = 16; o > 0; o >>= 1)
        vmax = fmaxf(vmax, __shfl_xor_sync(0xffffffffu, vmax, o));

    float es = __expf(acc0 - vmax) + ((lane < 8) ? __expf(acc1 - vmax) : 0.f);
    #pragma unroll
    for (int o = 16; o > 0; o >>= 1)
        es += __shfl_xor_sync(0xffffffffu, es, o);

    float lse = vmax + __logf(es);
    out[(size_t)warp * NCLS + c0] = acc0 - lse;
    if (lane < 8) out[(size_t)warp * NCLS + lane + 32] = acc1 - lse;
}

// ---------------- host launch ----------------
extern "C" void kernel_launch(void* const* d_in, const int* in_sizes, int n_in,
                              void* d_out, int out_size)
{
    const float* x         = (const float*)d_in[0];
    const void*  edge_idx  = d_in[1];
    const float* edge_attr = (const float*)d_in[2];
    const float* eps1 = (const float*)d_in[3];
    const float* We1  = (const float*)d_in[4];
    const float* be1  = (const float*)d_in[5];
    const float* W11  = (const float*)d_in[6];
    const float* b11  = (const float*)d_in[7];
    const float* W12  = (const float*)d_in[8];
    const float* b12  = (const float*)d_in[9];
    const float* eps2 = (const float*)d_in[10];
    const float* We2  = (const float*)d_in[11];
    const float* be2  = (const float*)d_in[12];
    const float* W21  = (const float*)d_in[13];
    const float* b21  = (const float*)d_in[14];
    const float* W22  = (const float*)d_in[15];
    const float* b22  = (const float*)d_in[16];
    const float* Wl   = (const float*)d_in[17];
    const float* bl   = (const float*)d_in[18];
    float* out = (float*)d_out;

    const int N = in_sizes[0] / F;
    const int E = in_sizes[2];

    // resolve device scratch addresses
    static float *buf_a = nullptr, *buf_b = nullptr;
    if (!buf_a) {
        cudaGetSymbolAddress((void**)&buf_a, g_buf_a);
        cudaGetSymbolAddress((void**)&buf_b, g_buf_b);
        size_t smem = 2 * 128 * SLD * sizeof(float);
        cudaFuncSetAttribute(mlp_kernel, cudaFuncAttributeMaxDynamicSharedMemorySize, (int)smem);
    }
    const size_t smem = 2 * 128 * SLD * sizeof(float);

    const int TB = 256;
    int ebl = (E + TB - 1) / TB;
    int nbl = (N + TB) / TB;           // covers N+1 for zeroing
    int wbl = (N * 32 + TB - 1) / TB;  // warp-per-node grids
    int mbl = (N + 127) / 128;

    // CSR build (shared by both convs)
    detect_kernel<<<1, 256>>>((const unsigned int*)edge_idx);
    extract_kernel<<<ebl, TB>>>(edge_idx, E);
    zero_counts_kernel<<<nbl, TB>>>(N);
    hist_kernel<<<ebl, TB>>>(E);
    scan_kernel<<<1, 1024>>>(N);
    scatter_kernel<<<ebl, TB>>>(edge_attr, E);

    // conv1
    agg_kernel<<<wbl, TB>>>((const float4*)x, We1, be1, eps1, (float4*)buf_a, N);
    mlp_kernel<<<mbl, TB, smem>>>(buf_a, W11, b11, W12, b12, buf_b, N);
    // conv2
    agg_kernel<<<wbl, TB>>>((const float4*)buf_b, We2, be2, eps2, (float4*)buf_a, N);
    mlp_kernel<<<mbl, TB, smem>>>(buf_a, W21, b21, W22, b22, buf_b, N);
    // classifier + log_softmax
    cls_kernel<<<wbl, TB>>>(buf_b, Wl, bl, out, N);
}

// round 3
// speedup vs baseline: 1.0738x; 1.0738x over previous
#include <cuda_runtime.h>
#include <math_constants.h>
#include <stdint.h>

// Problem constants (max sizes for static scratch; actual sizes derived from in_sizes)
#define MAXN 100000
#define MAXE 1600000
#define F 128
#define F4 32            // F/4
#define NCLS 40

// ---------------- device scratch (no allocations allowed) ----------------
__device__ int   g_is64;
__device__ int   g_src[MAXE];
__device__ int   g_dst[MAXE];
__device__ int   g_perm_src[MAXE];
__device__ float g_perm_ea[MAXE];
__device__ int   g_counts[MAXN + 1];
__device__ int   g_offsets[MAXN + 1];
__device__ int   g_cursor[MAXN];
__device__ float g_buf_a[(size_t)MAXN * F];
__device__ float g_buf_b[(size_t)MAXN * F];

// ---------------- dtype detection: int64 vs int32 edge_index ----------------
__global__ void detect_kernel(const unsigned int* __restrict__ ei) {
    __shared__ int any_nonzero;
    if (threadIdx.x == 0) any_nonzero = 0;
    __syncthreads();
    for (int i = threadIdx.x; i < 1024; i += blockDim.x) {
        if (ei[2 * i + 1] != 0u) any_nonzero = 1;
    }
    __syncthreads();
    if (threadIdx.x == 0) g_is64 = (any_nonzero == 0) ? 1 : 0;
}

__global__ void extract_kernel(const void* __restrict__ ei, int E) {
    int e = blockIdx.x * blockDim.x + threadIdx.x;
    if (e >= E) return;
    if (g_is64) {
        const long long* p = (const long long*)ei;
        g_src[e] = (int)p[e];
        g_dst[e] = (int)p[(size_t)E + e];
    } else {
        const int* p = (const int*)ei;
        g_src[e] = p[e];
        g_dst[e] = p[E + e];
    }
}

// ---------------- CSR build ----------------
__global__ void zero_counts_kernel(int n) {
    int i = blockIdx.x * blockDim.x + threadIdx.x;
    if (i <= n) g_counts[i] = 0;
}

__global__ void hist_kernel(int E) {
    int e = blockIdx.x * blockDim.x + threadIdx.x;
    if (e >= E) return;
    atomicAdd(&g_counts[g_dst[e]], 1);
}

__global__ void scan_kernel(int n) {
    __shared__ int sums[1024];
    int t = threadIdx.x;
    int CH = (n + 1023) / 1024;
    int start = t * CH; if (start > n) start = n;
    int end = start + CH; if (end > n) end = n;
    int s = 0;
    for (int i = start; i < end; i++) s += g_counts[i];
    sums[t] = s;
    __syncthreads();
    for (int off = 1; off < 1024; off <<= 1) {
        int v = 0;
        if (t >= off) v = sums[t - off];
        __syncthreads();
        sums[t] += v;
        __syncthreads();
    }
    int excl = sums[t] - s;
    int run = excl;
    for (int i = start; i < end; i++) {
        g_offsets[i] = run;
        g_cursor[i]  = run;
        run += g_counts[i];
    }
    if (t == 0) g_offsets[n] = sums[1023];
}

__global__ void scatter_kernel(const float* __restrict__ edge_attr, int E) {
    int e = blockIdx.x * blockDim.x + threadIdx.x;
    if (e >= E) return;
    int d = g_dst[e];
    int pos = atomicAdd(&g_cursor[d], 1);
    g_perm_src[pos] = g_src[e];
    g_perm_ea[pos]  = edge_attr[e];
}

// ---------------- GINE aggregation: warp per node, no float atomics ----------------
__global__ void __launch_bounds__(256) agg_kernel(
    const float4* __restrict__ xin, const float* __restrict__ We,
    const float* __restrict__ be, const float* __restrict__ eps_p,
    float4* __restrict__ out, int n)
{
    int warp = (blockIdx.x * blockDim.x + threadIdx.x) >> 5;
    int lane = threadIdx.x & 31;
    if (warp >= n) return;

    float4 w  = ((const float4*)We)[lane];
    float4 bb = ((const float4*)be)[lane];
    int beg = g_offsets[warp];
    int end = g_offsets[warp + 1];

    float4 acc = make_float4(0.f, 0.f, 0.f, 0.f);
    for (int p = beg; p < end; p++) {
        int   s  = g_perm_src[p];
        float ea = g_perm_ea[p];
        float4 xj = __ldg(&xin[(size_t)s * F4 + lane]);
        acc.x += fmaxf(fmaf(ea, w.x, xj.x) + bb.x, 0.f);
        acc.y += fmaxf(fmaf(ea, w.y, xj.y) + bb.y, 0.f);
        acc.z += fmaxf(fmaf(ea, w.z, xj.z) + bb.z, 0.f);
        acc.w += fmaxf(fmaf(ea, w.w, xj.w) + bb.w, 0.f);
    }
    float epv = 1.f + __ldg(eps_p);
    float4 xi = __ldg(&xin[(size_t)warp * F4 + lane]);
    float4 r;
    r.x = fmaf(epv, xi.x, acc.x);
    r.y = fmaf(epv, xi.y, acc.y);
    r.z = fmaf(epv, xi.z, acc.z);
    r.w = fmaf(epv, xi.w, acc.w);
    out[(size_t)warp * F4 + lane] = r;
}

// ---------------- tf32 tensor-core fused MLP ----------------
// Out = relu( relu(In@W1+b1) @ W2 + b2 ), 64-row tile, K=N=128.
// 3-product tf32 split for ~fp32 precision: D = Ahi*Bhi + Ahi*Blo + Alo*Bhi.

__device__ __forceinline__ uint32_t f2tf32(float x) {
    uint32_t r;
    asm("cvt.rna.tf32.f32 %0, %1;" : "=r"(r) : "f"(x));
    return r;
}
__device__ __forceinline__ void split_tf32(float x, uint32_t& hi, uint32_t& lo) {
    hi = f2tf32(x);
    lo = f2tf32(x - __uint_as_float(hi));
}
__device__ __forceinline__ void mma_tf32(float* d, const uint32_t* a, const uint32_t* b) {
    asm volatile(
        "mma.sync.aligned.m16n8k8.row.col.f32.tf32.tf32.f32 "
        "{%0,%1,%2,%3}, {%4,%5,%6,%7}, {%8,%9}, {%0,%1,%2,%3};"
        : "+f"(d[0]), "+f"(d[1]), "+f"(d[2]), "+f"(d[3])
        : "r"(a[0]), "r"(a[1]), "r"(a[2]), "r"(a[3]), "r"(b[0]), "r"(b[1]));
}

#define TM   64    // rows per block
#define SLDA 72    // As[k][m] stride (bank-conflict-free fragment loads)
#define SLDB 136   // Bs[k][n] stride
#define SMEM_MLP ((128 * SLDA + 128 * SLDB) * 4)

__global__ void __launch_bounds__(256, 2) mlp_kernel(
    const float* __restrict__ In,
    const float* __restrict__ W1, const float* __restrict__ b1,
    const float* __restrict__ W2, const float* __restrict__ b2,
    float* __restrict__ Out, int n)
{
    extern __shared__ float sm[];
    float* As = sm;                 // [128 k][TM m]
    float* Bs = sm + 128 * SLDA;    // [128 k][128 n]

    const int t    = threadIdx.x;
    const int lane = t & 31;
    const int wid  = t >> 5;
    const int wm   = wid & 1;       // 0/1 -> row half
    const int wn   = wid >> 1;      // 0..3 -> 32-col slab
    const int m0   = blockIdx.x * TM;
    const int lq   = lane & 3;      // quad index
    const int lg   = lane >> 2;     // group id

    // Load In tile transposed into As: 64 rows x 128 cols = 2048 float4
    #pragma unroll
    for (int r = 0; r < 8; r++) {
        int idx = t + r * 256;
        int m   = idx >> 5;
        int k4  = (idx & 31) * 4;
        float4 v = make_float4(0.f, 0.f, 0.f, 0.f);
        if (m0 + m < n) v = *(const float4*)(In + (size_t)(m0 + m) * F + k4);
        As[(k4 + 0) * SLDA + m] = v.x;
        As[(k4 + 1) * SLDA + m] = v.y;
        As[(k4 + 2) * SLDA + m] = v.z;
        As[(k4 + 3) * SLDA + m] = v.w;
    }
    // Load W1 into Bs
    #pragma unroll
    for (int r = 0; r < 16; r++) {
        int idx = t + r * 256;
        int k   = idx >> 5;
        int c4  = (idx & 31) * 4;
        *(float4*)(Bs + k * SLDB + c4) = *(const float4*)(W1 + k * F + c4);
    }
    __syncthreads();

    float acc[2][4][4];
    #pragma unroll
    for (int i = 0; i < 2; i++)
        #pragma unroll
        for (int j = 0; j < 4; j++)
            #pragma unroll
            for (int c = 0; c < 4; c++) acc[i][j][c] = 0.f;

    // ---- stage 1: T = In @ W1 ----
    #pragma unroll 4
    for (int ks = 0; ks < 128; ks += 8) {
        uint32_t ahi[2][4], alo[2][4], bhi[4][2], blo[4][2];
        #pragma unroll
        for (int mt = 0; mt < 2; mt++) {
            int mb = wm * 32 + mt * 16 + lg;
            const float* ap = As + (ks + lq) * SLDA + mb;
            split_tf32(ap[0],            ahi[mt][0], alo[mt][0]);
            split_tf32(ap[8],            ahi[mt][1], alo[mt][1]);
            split_tf32(ap[4 * SLDA],     ahi[mt][2], alo[mt][2]);
            split_tf32(ap[4 * SLDA + 8], ahi[mt][3], alo[mt][3]);
        }
        #pragma unroll
        for (int nt = 0; nt < 4; nt++) {
            int nb = wn * 32 + nt * 8 + lg;
            const float* bp = Bs + (ks + lq) * SLDB + nb;
            split_tf32(bp[0],        bhi[nt][0], blo[nt][0]);
            split_tf32(bp[4 * SLDB], bhi[nt][1], blo[nt][1]);
        }
        #pragma unroll
        for (int mt = 0; mt < 2; mt++)
            #pragma unroll
            for (int nt = 0; nt < 4; nt++) {
                mma_tf32(acc[mt][nt], ahi[mt], bhi[nt]);
                mma_tf32(acc[mt][nt], ahi[mt], blo[nt]);
                mma_tf32(acc[mt][nt], alo[mt], bhi[nt]);
            }
    }
    __syncthreads();

    // epilogue 1: t = relu(acc + b1), write transposed into As[k=hidden][m]
    #pragma unroll
    for (int mt = 0; mt < 2; mt++) {
        int r0 = wm * 32 + mt * 16 + lg;
        #pragma unroll
        for (int nt = 0; nt < 4; nt++) {
            int c = wn * 32 + nt * 8 + 2 * lq;
            float ba = __ldg(b1 + c), bb = __ldg(b1 + c + 1);
            As[(c    ) * SLDA + r0    ] = fmaxf(acc[mt][nt][0] + ba, 0.f);
            As[(c + 1) * SLDA + r0    ] = fmaxf(acc[mt][nt][1] + bb, 0.f);
            As[(c    ) * SLDA + r0 + 8] = fmaxf(acc[mt][nt][2] + ba, 0.f);
            As[(c + 1) * SLDA + r0 + 8] = fmaxf(acc[mt][nt][3] + bb, 0.f);
            acc[mt][nt][0] = 0.f; acc[mt][nt][1] = 0.f;
            acc[mt][nt][2] = 0.f; acc[mt][nt][3] = 0.f;
        }
    }
    // Load W2 into Bs
    #pragma unroll
    for (int r = 0; r < 16; r++) {
        int idx = t + r * 256;
        int k   = idx >> 5;
        int c4  = (idx & 31) * 4;
        *(float4*)(Bs + k * SLDB + c4) = *(const float4*)(W2 + k * F + c4);
    }
    __syncthreads();

    // ---- stage 2: Out = relu(T @ W2 + b2) ----
    #pragma unroll 4
    for (int ks = 0; ks < 128; ks += 8) {
        uint32_t ahi[2][4], alo[2][4], bhi[4][2], blo[4][2];
        #pragma unroll
        for (int mt = 0; mt < 2; mt++) {
            int mb = wm * 32 + mt * 16 + lg;
            const float* ap = As + (ks + lq) * SLDA + mb;
            split_tf32(ap[0],            ahi[mt][0], alo[mt][0]);
            split_tf32(ap[8],            ahi[mt][1], alo[mt][1]);
            split_tf32(ap[4 * SLDA],     ahi[mt][2], alo[mt][2]);
            split_tf32(ap[4 * SLDA + 8], ahi[mt][3], alo[mt][3]);
        }
        #pragma unroll
        for (int nt = 0; nt < 4; nt++) {
            int nb = wn * 32 + nt * 8 + lg;
            const float* bp = Bs + (ks + lq) * SLDB + nb;
            split_tf32(bp[0],        bhi[nt][0], blo[nt][0]);
            split_tf32(bp[4 * SLDB], bhi[nt][1], blo[nt][1]);
        }
        #pragma unroll
        for (int mt = 0; mt < 2; mt++)
            #pragma unroll
            for (int nt = 0; nt < 4; nt++) {
                mma_tf32(acc[mt][nt], ahi[mt], bhi[nt]);
                mma_tf32(acc[mt][nt], ahi[mt], blo[nt]);
                mma_tf32(acc[mt][nt], alo[mt], bhi[nt]);
            }
    }

    // epilogue 2: Out = relu(acc + b2)
    #pragma unroll
    for (int mt = 0; mt < 2; mt++) {
        int r0 = m0 + wm * 32 + mt * 16 + lg;
        #pragma unroll
        for (int nt = 0; nt < 4; nt++) {
            int c = wn * 32 + nt * 8 + 2 * lq;
            float ba = __ldg(b2 + c), bb = __ldg(b2 + c + 1);
            if (r0 < n) {
                float2 v;
                v.x = fmaxf(acc[mt][nt][0] + ba, 0.f);
                v.y = fmaxf(acc[mt][nt][1] + bb, 0.f);
                *(float2*)(Out + (size_t)r0 * F + c) = v;
            }
            if (r0 + 8 < n) {
                float2 v;
                v.x = fmaxf(acc[mt][nt][2] + ba, 0.f);
                v.y = fmaxf(acc[mt][nt][3] + bb, 0.f);
                *(float2*)(Out + (size_t)(r0 + 8) * F + c) = v;
            }
        }
    }
}

// ---------------- classifier + log_softmax: warp per node ----------------
__global__ void __launch_bounds__(256) cls_kernel(
    const float* __restrict__ H, const float* __restrict__ Wl,
    const float* __restrict__ bl, float* __restrict__ out, int n)
{
    int warp = (blockIdx.x * blockDim.x + threadIdx.x) >> 5;
    int lane = threadIdx.x & 31;
    if (warp >= n) return;

    int c0 = lane;
    int c1 = (lane < 8) ? (lane + 32) : 0;
    float acc0 = bl[c0];
    float acc1 = (lane < 8) ? bl[lane + 32] : 0.f;

    const float4* H4 = (const float4*)(H + (size_t)warp * F);
    #pragma unroll 8
    for (int kk = 0; kk < 32; kk++) {
        float4 h = __ldg(&H4[kk]);
        int k = kk * 4;
        acc0 = fmaf(h.x, Wl[(k + 0) * NCLS + c0], acc0);
        acc0 = fmaf(h.y, Wl[(k + 1) * NCLS + c0], acc0);
        acc0 = fmaf(h.z, Wl[(k + 2) * NCLS + c0], acc0);
        acc0 = fmaf(h.w, Wl[(k + 3) * NCLS + c0], acc0);
        acc1 = fmaf(h.x, Wl[(k + 0) * NCLS + c1], acc1);
        acc1 = fmaf(h.y, Wl[(k + 1) * NCLS + c1], acc1);
        acc1 = fmaf(h.z, Wl[(k + 2) * NCLS + c1], acc1);
        acc1 = fmaf(h.w, Wl[(k + 3) * NCLS + c1], acc1);
    }

    float vmax = fmaxf(acc0, (lane < 8) ? acc1 : -CUDART_INF_F);
    #pragma unroll
    for (int o = 16; o > 0; o >>= 1)
        vmax = fmaxf(vmax, __shfl_xor_sync(0xffffffffu, vmax, o));

    float es = __expf(acc0 - vmax) + ((lane < 8) ? __expf(acc1 - vmax) : 0.f);
    #pragma unroll
    for (int o = 16; o > 0; o >>= 1)
        es += __shfl_xor_sync(0xffffffffu, es, o);

    float lse = vmax + __logf(es);
    out[(size_t)warp * NCLS + c0] = acc0 - lse;
    if (lane < 8) out[(size_t)warp * NCLS + lane + 32] = acc1 - lse;
}

// ---------------- host launch ----------------
extern "C" void kernel_launch(void* const* d_in, const int* in_sizes, int n_in,
                              void* d_out, int out_size)
{
    const float* x         = (const float*)d_in[0];
    const void*  edge_idx  = d_in[1];
    const float* edge_attr = (const float*)d_in[2];
    const float* eps1 = (const float*)d_in[3];
    const float* We1  = (const float*)d_in[4];
    const float* be1  = (const float*)d_in[5];
    const float* W11  = (const float*)d_in[6];
    const float* b11  = (const float*)d_in[7];
    const float* W12  = (const float*)d_in[8];
    const float* b12  = (const float*)d_in[9];
    const float* eps2 = (const float*)d_in[10];
    const float* We2  = (const float*)d_in[11];
    const float* be2  = (const float*)d_in[12];
    const float* W21  = (const float*)d_in[13];
    const float* b21  = (const float*)d_in[14];
    const float* W22  = (const float*)d_in[15];
    const float* b22  = (const float*)d_in[16];
    const float* Wl   = (const float*)d_in[17];
    const float* bl   = (const float*)d_in[18];
    float* out = (float*)d_out;

    const int N = in_sizes[0] / F;
    const int E = in_sizes[2];

    static float *buf_a = nullptr, *buf_b = nullptr;
    if (!buf_a) {
        cudaGetSymbolAddress((void**)&buf_a, g_buf_a);
        cudaGetSymbolAddress((void**)&buf_b, g_buf_b);
        cudaFuncSetAttribute(mlp_kernel, cudaFuncAttributeMaxDynamicSharedMemorySize, SMEM_MLP);
    }

    const int TB = 256;
    int ebl = (E + TB - 1) / TB;
    int nbl = (N + TB) / TB;
    int wbl = (N * 32 + TB - 1) / TB;
    int mbl = (N + TM - 1) / TM;

    // CSR build (shared by both convs)
    detect_kernel<<<1, 256>>>((const unsigned int*)edge_idx);
    extract_kernel<<<ebl, TB>>>(edge_idx, E);
    zero_counts_kernel<<<nbl, TB>>>(N);
    hist_kernel<<<ebl, TB>>>(E);
    scan_kernel<<<1, 1024>>>(N);
    scatter_kernel<<<ebl, TB>>>(edge_attr, E);

    // conv1
    agg_kernel<<<wbl, TB>>>((const float4*)x, We1, be1, eps1, (float4*)buf_a, N);
    mlp_kernel<<<mbl, TB, SMEM_MLP>>>(buf_a, W11, b11, W12, b12, buf_b, N);
    // conv2
    agg_kernel<<<wbl, TB>>>((const float4*)buf_b, We2, be2, eps2, (float4*)buf_a, N);
    mlp_kernel<<<mbl, TB, SMEM_MLP>>>(buf_a, W21, b21, W22, b22, buf_b, N);
    // classifier + log_softmax
    cls_kernel<<<wbl, TB>>>(buf_b, Wl, bl, out, N);
}

// round 6
// speedup vs baseline: 1.4206x; 1.3231x over previous
#include <cuda_runtime.h>
#include <math_constants.h>
#include <stdint.h>

#define MAXN 100000
#define MAXE 1600000
#define F 128
#define F4 32
#define NCLS 40

// ---------------- device scratch ----------------
__device__ int   g_is64;
__device__ int   g_src[MAXE];
__device__ int   g_dst[MAXE];
__device__ int   g_perm_src[MAXE];
__device__ float g_perm_ea[MAXE];
__device__ int   g_counts[MAXN + 1];
__device__ int   g_offsets[MAXN + 1];
__device__ int   g_cursor[MAXN];
__device__ float g_buf_a[(size_t)MAXN * F];
__device__ float g_buf_b[(size_t)MAXN * F];

// ---------------- dtype detection ----------------
__global__ void detect_kernel(const unsigned int* __restrict__ ei) {
    __shared__ int any_nonzero;
    if (threadIdx.x == 0) any_nonzero = 0;
    __syncthreads();
    for (int i = threadIdx.x; i < 1024; i += blockDim.x) {
        if (ei[2 * i + 1] != 0u) any_nonzero = 1;
    }
    __syncthreads();
    if (threadIdx.x == 0) g_is64 = (any_nonzero == 0) ? 1 : 0;
}

__global__ void extract_kernel(const void* __restrict__ ei, int E) {
    int e = blockIdx.x * blockDim.x + threadIdx.x;
    if (e >= E) return;
    if (g_is64) {
        const long long* p = (const long long*)ei;
        g_src[e] = (int)p[e];
        g_dst[e] = (int)p[(size_t)E + e];
    } else {
        const int* p = (const int*)ei;
        g_src[e] = p[e];
        g_dst[e] = p[E + e];
    }
}

// ---------------- CSR build ----------------
__global__ void zero_counts_kernel(int n) {
    int i = blockIdx.x * blockDim.x + threadIdx.x;
    if (i <= n) g_counts[i] = 0;
}

__global__ void hist_kernel(int E) {
    int e = blockIdx.x * blockDim.x + threadIdx.x;
    if (e >= E) return;
    atomicAdd(&g_counts[g_dst[e]], 1);
}

__global__ void scan_kernel(int n) {
    __shared__ int sums[1024];
    int t = threadIdx.x;
    int CH = (n + 1023) / 1024;
    int start = t * CH; if (start > n) start = n;
    int end = start + CH; if (end > n) end = n;
    int s = 0;
    for (int i = start; i < end; i++) s += g_counts[i];
    sums[t] = s;
    __syncthreads();
    for (int off = 1; off < 1024; off <<= 1) {
        int v = 0;
        if (t >= off) v = sums[t - off];
        __syncthreads();
        sums[t] += v;
        __syncthreads();
    }
    int excl = sums[t] - s;
    int run = excl;
    for (int i = start; i < end; i++) {
        g_offsets[i] = run;
        g_cursor[i]  = run;
        run += g_counts[i];
    }
    if (t == 0) g_offsets[n] = sums[1023];
}

__global__ void scatter_kernel(const float* __restrict__ edge_attr, int E) {
    int e = blockIdx.x * blockDim.x + threadIdx.x;
    if (e >= E) return;
    int d = g_dst[e];
    int pos = atomicAdd(&g_cursor[d], 1);
    g_perm_src[pos] = g_src[e];
    g_perm_ea[pos]  = edge_attr[e];
}

// ---------------- GINE aggregation: warp per node, unroll-4 for MLP ----------------
__global__ void __launch_bounds__(256) agg_kernel(
    const float4* __restrict__ xin, const float* __restrict__ We,
    const float* __restrict__ be, const float* __restrict__ eps_p,
    float4* __restrict__ out, int n)
{
    int warp = (blockIdx.x * blockDim.x + threadIdx.x) >> 5;
    int lane = threadIdx.x & 31;
    if (warp >= n) return;

    float4 w  = ((const float4*)We)[lane];
    float4 bb = ((const float4*)be)[lane];
    int beg = g_offsets[warp];
    int end = g_offsets[warp + 1];

    float4 acc = make_float4(0.f, 0.f, 0.f, 0.f);
    int p = beg;
    for (; p + 3 < end; p += 4) {
        int s0 = g_perm_src[p];
        int s1 = g_perm_src[p + 1];
        int s2 = g_perm_src[p + 2];
        int s3 = g_perm_src[p + 3];
        float e0 = g_perm_ea[p];
        float e1 = g_perm_ea[p + 1];
        float e2 = g_perm_ea[p + 2];
        float e3 = g_perm_ea[p + 3];
        float4 x0 = __ldg(&xin[(size_t)s0 * F4 + lane]);
        float4 x1 = __ldg(&xin[(size_t)s1 * F4 + lane]);
        float4 x2 = __ldg(&xin[(size_t)s2 * F4 + lane]);
        float4 x3 = __ldg(&xin[(size_t)s3 * F4 + lane]);
        acc.x += fmaxf(fmaf(e0, w.x, x0.x) + bb.x, 0.f);
        acc.y += fmaxf(fmaf(e0, w.y, x0.y) + bb.y, 0.f);
        acc.z += fmaxf(fmaf(e0, w.z, x0.z) + bb.z, 0.f);
        acc.w += fmaxf(fmaf(e0, w.w, x0.w) + bb.w, 0.f);
        acc.x += fmaxf(fmaf(e1, w.x, x1.x) + bb.x, 0.f);
        acc.y += fmaxf(fmaf(e1, w.y, x1.y) + bb.y, 0.f);
        acc.z += fmaxf(fmaf(e1, w.z, x1.z) + bb.z, 0.f);
        acc.w += fmaxf(fmaf(e1, w.w, x1.w) + bb.w, 0.f);
        acc.x += fmaxf(fmaf(e2, w.x, x2.x) + bb.x, 0.f);
        acc.y += fmaxf(fmaf(e2, w.y, x2.y) + bb.y, 0.f);
        acc.z += fmaxf(fmaf(e2, w.z, x2.z) + bb.z, 0.f);
        acc.w += fmaxf(fmaf(e2, w.w, x2.w) + bb.w, 0.f);
        acc.x += fmaxf(fmaf(e3, w.x, x3.x) + bb.x, 0.f);
        acc.y += fmaxf(fmaf(e3, w.y, x3.y) + bb.y, 0.f);
        acc.z += fmaxf(fmaf(e3, w.z, x3.z) + bb.z, 0.f);
        acc.w += fmaxf(fmaf(e3, w.w, x3.w) + bb.w, 0.f);
    }
    for (; p < end; p++) {
        int   s  = g_perm_src[p];
        float ea = g_perm_ea[p];
        float4 xj = __ldg(&xin[(size_t)s * F4 + lane]);
        acc.x += fmaxf(fmaf(ea, w.x, xj.x) + bb.x, 0.f);
        acc.y += fmaxf(fmaf(ea, w.y, xj.y) + bb.y, 0.f);
        acc.z += fmaxf(fmaf(ea, w.z, xj.z) + bb.z, 0.f);
        acc.w += fmaxf(fmaf(ea, w.w, xj.w) + bb.w, 0.f);
    }
    float epv = 1.f + __ldg(eps_p);
    float4 xi = __ldg(&xin[(size_t)warp * F4 + lane]);
    float4 r;
    r.x = fmaf(epv, xi.x, acc.x);
    r.y = fmaf(epv, xi.y, acc.y);
    r.z = fmaf(epv, xi.z, acc.z);
    r.w = fmaf(epv, xi.w, acc.w);
    out[(size_t)warp * F4 + lane] = r;
}

// ---------------- tf32 helpers ----------------
__device__ __forceinline__ uint32_t f2tf32(float x) {
    uint32_t r;
    asm("cvt.rna.tf32.f32 %0, %1;" : "=r"(r) : "f"(x));
    return r;
}
__device__ __forceinline__ void split_tf32(float x, uint32_t& hi, uint32_t& lo) {
    hi = f2tf32(x);
    lo = f2tf32(x - __uint_as_float(hi));
}
__device__ __forceinline__ void mma_tf32(float* d, const uint32_t* a, const uint32_t* b) {
    asm volatile(
        "mma.sync.aligned.m16n8k8.row.col.f32.tf32.tf32.f32 "
        "{%0,%1,%2,%3}, {%4,%5,%6,%7}, {%8,%9}, {%0,%1,%2,%3};"
        : "+f"(d[0]), "+f"(d[1]), "+f"(d[2]), "+f"(d[3])
        : "r"(a[0]), "r"(a[1]), "r"(a[2]), "r"(a[3]), "r"(b[0]), "r"(b[1]));
}

// ---------------- tf32 tensor-core fused MLP (A row-major, conflict-free) ----------------
#define TM   64
#define SLDK 132   // As[m][k] row stride: frag addr 4*lg+lq spans all banks
#define SLDB 136   // Bs[k][n] row stride
#define SMEM_MLP ((TM * SLDK + 128 * SLDB) * 4)

__global__ void __launch_bounds__(256, 2) mlp_kernel(
    const float* __restrict__ In,
    const float* __restrict__ W1, const float* __restrict__ b1,
    const float* __restrict__ W2, const float* __restrict__ b2,
    float* __restrict__ Out, int n)
{
    extern __shared__ float sm[];
    float* As = sm;                // [TM m][128 k] row-major
    float* Bs = sm + TM * SLDK;    // [128 k][128 n]

    const int t    = threadIdx.x;
    const int lane = t & 31;
    const int wid  = t >> 5;
    const int wm   = wid & 1;
    const int wn   = wid >> 1;
    const int m0   = blockIdx.x * TM;
    const int lq   = lane & 3;
    const int lg   = lane >> 2;

    // Load In tile row-major (conflict-free float4 stores)
    #pragma unroll
    for (int r = 0; r < 8; r++) {
        int idx = t + r * 256;
        int m   = idx >> 5;
        int k4  = (idx & 31) * 4;
        float4 v = make_float4(0.f, 0.f, 0.f, 0.f);
        if (m0 + m < n) v = *(const float4*)(In + (size_t)(m0 + m) * F + k4);
        *(float4*)(As + m * SLDK + k4) = v;
    }
    // Load W1 into Bs
    #pragma unroll
    for (int r = 0; r < 16; r++) {
        int idx = t + r * 256;
        int k   = idx >> 5;
        int c4  = (idx & 31) * 4;
        *(float4*)(Bs + k * SLDB + c4) = *(const float4*)(W1 + k * F + c4);
    }
    __syncthreads();

    float acc[2][4][4];
    #pragma unroll
    for (int i = 0; i < 2; i++)
        #pragma unroll
        for (int j = 0; j < 4; j++)
            #pragma unroll
            for (int c = 0; c < 4; c++) acc[i][j][c] = 0.f;

    // ---- stage 1: T = In @ W1 ----
    #pragma unroll 4
    for (int ks = 0; ks < 128; ks += 8) {
        uint32_t ahi[2][4], alo[2][4], bhi[4][2], blo[4][2];
        #pragma unroll
        for (int mt = 0; mt < 2; mt++) {
            int mb = wm * 32 + mt * 16 + lg;
            const float* ap = As + mb * SLDK + ks + lq;
            split_tf32(ap[0],            ahi[mt][0], alo[mt][0]);
            split_tf32(ap[8 * SLDK],     ahi[mt][1], alo[mt][1]);
            split_tf32(ap[4],            ahi[mt][2], alo[mt][2]);
            split_tf32(ap[8 * SLDK + 4], ahi[mt][3], alo[mt][3]);
        }
        #pragma unroll
        for (int nt = 0; nt < 4; nt++) {
            int nb = wn * 32 + nt * 8 + lg;
            const float* bp = Bs + (ks + lq) * SLDB + nb;
            split_tf32(bp[0],        bhi[nt][0], blo[nt][0]);
            split_tf32(bp[4 * SLDB], bhi[nt][1], blo[nt][1]);
        }
        #pragma unroll
        for (int mt = 0; mt < 2; mt++)
            #pragma unroll
            for (int nt = 0; nt < 4; nt++) {
                mma_tf32(acc[mt][nt], ahi[mt], bhi[nt]);
                mma_tf32(acc[mt][nt], ahi[mt], blo[nt]);
                mma_tf32(acc[mt][nt], alo[mt], bhi[nt]);
            }
    }
    __syncthreads();

    // epilogue 1: T = relu(acc + b1) stored row-major into As[m][hidden]
    #pragma unroll
    for (int mt = 0; mt < 2; mt++) {
        int r0 = wm * 32 + mt * 16 + lg;
        #pragma unroll
        for (int nt = 0; nt < 4; nt++) {
            int c = wn * 32 + nt * 8 + 2 * lq;
            float ba = __ldg(b1 + c), bb = __ldg(b1 + c + 1);
            float2 v0, v1;
            v0.x = fmaxf(acc[mt][nt][0] + ba, 0.f);
            v0.y = fmaxf(acc[mt][nt][1] + bb, 0.f);
            v1.x = fmaxf(acc[mt][nt][2] + ba, 0.f);
            v1.y = fmaxf(acc[mt][nt][3] + bb, 0.f);
            *(float2*)(As + r0 * SLDK + c)       = v0;
            *(float2*)(As + (r0 + 8) * SLDK + c) = v1;
            acc[mt][nt][0] = 0.f; acc[mt][nt][1] = 0.f;
            acc[mt][nt][2] = 0.f; acc[mt][nt][3] = 0.f;
        }
    }
    // Load W2 into Bs
    #pragma unroll
    for (int r = 0; r < 16; r++) {
        int idx = t + r * 256;
        int k   = idx >> 5;
        int c4  = (idx & 31) * 4;
        *(float4*)(Bs + k * SLDB + c4) = *(const float4*)(W2 + k * F + c4);
    }
    __syncthreads();

    // ---- stage 2: Out = relu(T @ W2 + b2) ----
    #pragma unroll 4
    for (int ks = 0; ks < 128; ks += 8) {
        uint32_t ahi[2][4], alo[2][4], bhi[4][2], blo[4][2];
        #pragma unroll
        for (int mt = 0; mt < 2; mt++) {
            int mb = wm * 32 + mt * 16 + lg;
            const float* ap = As + mb * SLDK + ks + lq;
            split_tf32(ap[0],            ahi[mt][0], alo[mt][0]);
            split_tf32(ap[8 * SLDK],     ahi[mt][1], alo[mt][1]);
            split_tf32(ap[4],            ahi[mt][2], alo[mt][2]);
            split_tf32(ap[8 * SLDK + 4], ahi[mt][3], alo[mt][3]);
        }
        #pragma unroll
        for (int nt = 0; nt < 4; nt++) {
            int nb = wn * 32 + nt * 8 + lg;
            const float* bp = Bs + (ks + lq) * SLDB + nb;
            split_tf32(bp[0],        bhi[nt][0], blo[nt][0]);
            split_tf32(bp[4 * SLDB], bhi[nt][1], blo[nt][1]);
        }
        #pragma unroll
        for (int mt = 0; mt < 2; mt++)
            #pragma unroll
            for (int nt = 0; nt < 4; nt++) {
                mma_tf32(acc[mt][nt], ahi[mt], bhi[nt]);
                mma_tf32(acc[mt][nt], ahi[mt], blo[nt]);
                mma_tf32(acc[mt][nt], alo[mt], bhi[nt]);
            }
    }

    // epilogue 2
    #pragma unroll
    for (int mt = 0; mt < 2; mt++) {
        int r0 = m0 + wm * 32 + mt * 16 + lg;
        #pragma unroll
        for (int nt = 0; nt < 4; nt++) {
            int c = wn * 32 + nt * 8 + 2 * lq;
            float ba = __ldg(b2 + c), bb = __ldg(b2 + c + 1);
            if (r0 < n) {
                float2 v;
                v.x = fmaxf(acc[mt][nt][0] + ba, 0.f);
                v.y = fmaxf(acc[mt][nt][1] + bb, 0.f);
                *(float2*)(Out + (size_t)r0 * F + c) = v;
            }
            if (r0 + 8 < n) {
                float2 v;
                v.x = fmaxf(acc[mt][nt][2] + ba, 0.f);
                v.y = fmaxf(acc[mt][nt][3] + bb, 0.f);
                *(float2*)(Out + (size_t)(r0 + 8) * F + c) = v;
            }
        }
    }
}

// ---------------- classifier + log_softmax: tiled tf32 MMA ----------------
// 64-row tile, K=128, N=40 (5 x n8 tiles), 128 threads (4 warps, 16 rows each).
#define CLSK 132
#define LSLD 44
#define SMEM_CLS ((64 * CLSK + 128 * NCLS + 64 * LSLD + NCLS) * 4)

__global__ void __launch_bounds__(128) cls_mma_kernel(
    const float* __restrict__ H, const float* __restrict__ Wl,
    const float* __restrict__ bl, float* __restrict__ out, int n)
{
    extern __shared__ float sm[];
    float* Hs  = sm;                         // [64][CLSK]
    float* Ws  = Hs + 64 * CLSK;             // [128][40]
    float* Ls  = Ws + 128 * NCLS;            // [64][LSLD] logits
    float* bls = Ls + 64 * LSLD;             // [40]

    const int t    = threadIdx.x;
    const int lane = t & 31;
    const int wid  = t >> 5;                 // 0..3
    const int m0   = blockIdx.x * 64;
    const int lq   = lane & 3;
    const int lg   = lane >> 2;

    // Load H tile row-major: 64 x 128 = 2048 float4 over 128 threads
    #pragma unroll
    for (int r = 0; r < 16; r++) {
        int idx = t + r * 128;
        int m   = idx >> 5;
        int k4  = (idx & 31) * 4;
        float4 v = make_float4(0.f, 0.f, 0.f, 0.f);
        if (m0 + m < n) v = *(const float4*)(H + (size_t)(m0 + m) * F + k4);
        *(float4*)(Hs + m * CLSK + k4) = v;
    }
    // Load Wl (128x40 contiguous = 1280 float4)
    #pragma unroll
    for (int r = 0; r < 10; r++) {
        int idx = t + r * 128;
        ((float4*)Ws)[idx] = ((const float4*)Wl)[idx];
    }
    if (t < NCLS) bls[t] = bl[t];
    __syncthreads();

    const int mb = wid * 16;
    float acc[5][4];
    #pragma unroll
    for (int j = 0; j < 5; j++)
        #pragma unroll
        for (int c = 0; c < 4; c++) acc[j][c] = 0.f;

    #pragma unroll 4
    for (int ks = 0; ks < 128; ks += 8) {
        uint32_t ahi[4], alo[4], bhi[5][2], blo[5][2];
        const float* ap = Hs + (mb + lg) * CLSK + ks + lq;
        split_tf32(ap[0],            ahi[0], alo[0]);
        split_tf32(ap[8 * CLSK],     ahi[1], alo[1]);
        split_tf32(ap[4],            ahi[2], alo[2]);
        split_tf32(ap[8 * CLSK + 4], ahi[3], alo[3]);
        #pragma unroll
        for (int nt = 0; nt < 5; nt++) {
            const float* bp = Ws + (ks + lq) * NCLS + nt * 8 + lg;
            split_tf32(bp[0],        bhi[nt][0], blo[nt][0]);
            split_tf32(bp[4 * NCLS], bhi[nt][1], blo[nt][1]);
        }
        #pragma unroll
        for (int nt = 0; nt < 5; nt++) {
            mma_tf32(acc[nt], ahi, bhi[nt]);
            mma_tf32(acc[nt], ahi, blo[nt]);
            mma_tf32(acc[nt], alo, bhi[nt]);
        }
    }

    // epilogue: logits -> smem
    #pragma unroll
    for (int nt = 0; nt < 5; nt++) {
        int c = nt * 8 + 2 * lq;
        float ba = bls[c], bb = bls[c + 1];
        Ls[(mb + lg) * LSLD + c]         = acc[nt][0] + ba;
        Ls[(mb + lg) * LSLD + c + 1]     = acc[nt][1] + bb;
        Ls[(mb + lg + 8) * LSLD + c]     = acc[nt][2] + ba;
        Ls[(mb + lg + 8) * LSLD + c + 1] = acc[nt][3] + bb;
    }
    __syncthreads();

    // log_softmax: threads 0..63, one row each
    if (t < 64 && m0 + t < n) {
        const float* row = Ls + t * LSLD;
        float vmax = row[0];
        #pragma unroll
        for (int i = 1; i < NCLS; i++) vmax = fmaxf(vmax, row[i]);
        float es = 0.f;
        #pragma unroll
        for (int i = 0; i < NCLS; i++) es += __expf(row[i] - vmax);
        float lse = vmax + __logf(es);
        float* op = out + (size_t)(m0 + t) * NCLS;
        #pragma unroll
        for (int i = 0; i < NCLS; i++) op[i] = row[i] - lse;
    }
}

// ---------------- host launch ----------------
extern "C" void kernel_launch(void* const* d_in, const int* in_sizes, int n_in,
                              void* d_out, int out_size)
{
    const float* x         = (const float*)d_in[0];
    const void*  edge_idx  = d_in[1];
    const float* edge_attr = (const float*)d_in[2];
    const float* eps1 = (const float*)d_in[3];
    const float* We1  = (const float*)d_in[4];
    const float* be1  = (const float*)d_in[5];
    const float* W11  = (const float*)d_in[6];
    const float* b11  = (const float*)d_in[7];
    const float* W12  = (const float*)d_in[8];
    const float* b12  = (const float*)d_in[9];
    const float* eps2 = (const float*)d_in[10];
    const float* We2  = (const float*)d_in[11];
    const float* be2  = (const float*)d_in[12];
    const float* W21  = (const float*)d_in[13];
    const float* b21  = (const float*)d_in[14];
    const float* W22  = (const float*)d_in[15];
    const float* b22  = (const float*)d_in[16];
    const float* Wl   = (const float*)d_in[17];
    const float* bl   = (const float*)d_in[18];
    float* out = (float*)d_out;

    const int N = in_sizes[0] / F;
    const int E = in_sizes[2];

    static float *buf_a = nullptr, *buf_b = nullptr;
    if (!buf_a) {
        cudaGetSymbolAddress((void**)&buf_a, g_buf_a);
        cudaGetSymbolAddress((void**)&buf_b, g_buf_b);
        cudaFuncSetAttribute(mlp_kernel, cudaFuncAttributeMaxDynamicSharedMemorySize, SMEM_MLP);
        cudaFuncSetAttribute(cls_mma_kernel, cudaFuncAttributeMaxDynamicSharedMemorySize, SMEM_CLS);
    }

    const int TB = 256;
    int ebl = (E + TB - 1) / TB;
    int nbl = (N + TB) / TB;
    int wbl = (N * 32 + TB - 1) / TB;
    int mbl = (N + TM - 1) / TM;
    int cbl = (N + 63) / 64;

    // CSR build
    detect_kernel<<<1, 256>>>((const unsigned int*)edge_idx);
    extract_kernel<<<ebl, TB>>>(edge_idx, E);
    zero_counts_kernel<<<nbl, TB>>>(N);
    hist_kernel<<<ebl, TB>>>(E);
    scan_kernel<<<1, 1024>>>(N);
    scatter_kernel<<<ebl, TB>>>(edge_attr, E);

    // conv1
    agg_kernel<<<wbl, TB>>>((const float4*)x, We1, be1, eps1, (float4*)buf_a, N);
    mlp_kernel<<<mbl, TB, SMEM_MLP>>>(buf_a, W11, b11, W12, b12, buf_b, N);
    // conv2
    agg_kernel<<<wbl, TB>>>((const float4*)buf_b, We2, be2, eps2, (float4*)buf_a, N);
    mlp_kernel<<<mbl, TB, SMEM_MLP>>>(buf_a, W21, b21, W22, b22, buf_b, N);
    // classifier + log_softmax (tensor-core)
    cls_mma_kernel<<<cbl, 128, SMEM_CLS>>>(buf_b, Wl, bl, out, N);
}

// round 8
// speedup vs baseline: 1.4678x; 1.0332x over previous
#include <cuda_runtime.h>
#include <math_constants.h>
#include <stdint.h>

#define MAXN 100000
#define MAXE 1600000
#define F 128
#define F4 32
#define NCLS 40

// ---------------- device scratch ----------------
__device__ int   g_is64;
__device__ int   g_src[MAXE];
__device__ int   g_dst[MAXE];
__device__ int   g_perm_src[MAXE];
__device__ float g_perm_ea[MAXE];
__device__ int   g_counts[MAXN + 1];
__device__ int   g_offsets[MAXN + 1];
__device__ int   g_cursor[MAXN];
__device__ float g_buf_a[(size_t)MAXN * F];
__device__ float g_buf_b[(size_t)MAXN * F];

// ---------------- dtype detection ----------------
__global__ void detect_kernel(const unsigned int* __restrict__ ei) {
    __shared__ int any_nonzero;
    if (threadIdx.x == 0) any_nonzero = 0;
    __syncthreads();
    for (int i = threadIdx.x; i < 1024; i += blockDim.x) {
        if (ei[2 * i + 1] != 0u) any_nonzero = 1;
    }
    __syncthreads();
    if (threadIdx.x == 0) g_is64 = (any_nonzero == 0) ? 1 : 0;
}

__global__ void zero_counts_kernel(int n) {
    int i = blockIdx.x * blockDim.x + threadIdx.x;
    if (i <= n) g_counts[i] = 0;
}

// extract + histogram in one pass over E
__global__ void extract_hist_kernel(const void* __restrict__ ei, int E) {
    int e = blockIdx.x * blockDim.x + threadIdx.x;
    if (e >= E) return;
    int s, d;
    if (g_is64) {
        const long long* p = (const long long*)ei;
        s = (int)p[e];
        d = (int)p[(size_t)E + e];
    } else {
        const int* p = (const int*)ei;
        s = p[e];
        d = p[E + e];
    }
    g_src[e] = s;
    g_dst[e] = d;
    atomicAdd(&g_counts[d], 1);
}

__global__ void scan_kernel(int n) {
    __shared__ int sums[1024];
    int t = threadIdx.x;
    int CH = (n + 1023) / 1024;
    int start = t * CH; if (start > n) start = n;
    int end = start + CH; if (end > n) end = n;
    int s = 0;
    for (int i = start; i < end; i++) s += g_counts[i];
    sums[t] = s;
    __syncthreads();
    for (int off = 1; off < 1024; off <<= 1) {
        int v = 0;
        if (t >= off) v = sums[t - off];
        __syncthreads();
        sums[t] += v;
        __syncthreads();
    }
    int excl = sums[t] - s;
    int run = excl;
    for (int i = start; i < end; i++) {
        g_offsets[i] = run;
        g_cursor[i]  = run;
        run += g_counts[i];
    }
    if (t == 0) g_offsets[n] = sums[1023];
}

__global__ void scatter_kernel(const float* __restrict__ edge_attr, int E) {
    int e = blockIdx.x * blockDim.x + threadIdx.x;
    if (e >= E) return;
    int d = g_dst[e];
    int pos = atomicAdd(&g_cursor[d], 1);
    g_perm_src[pos] = g_src[e];
    g_perm_ea[pos]  = edge_attr[e];
}

// ---------------- GINE aggregation: warp per node, unroll-4 for MLP ----------------
__global__ void __launch_bounds__(256) agg_kernel(
    const float4* __restrict__ xin, const float* __restrict__ We,
    const float* __restrict__ be, const float* __restrict__ eps_p,
    float4* __restrict__ out, int n)
{
    int warp = (blockIdx.x * blockDim.x + threadIdx.x) >> 5;
    int lane = threadIdx.x & 31;
    if (warp >= n) return;

    float4 w  = ((const float4*)We)[lane];
    float4 bb = ((const float4*)be)[lane];
    int beg = g_offsets[warp];
    int end = g_offsets[warp + 1];

    float4 acc = make_float4(0.f, 0.f, 0.f, 0.f);
    int p = beg;
    for (; p + 3 < end; p += 4) {
        int s0 = g_perm_src[p];
        int s1 = g_perm_src[p + 1];
        int s2 = g_perm_src[p + 2];
        int s3 = g_perm_src[p + 3];
        float e0 = g_perm_ea[p];
        float e1 = g_perm_ea[p + 1];
        float e2 = g_perm_ea[p + 2];
        float e3 = g_perm_ea[p + 3];
        float4 x0 = __ldg(&xin[(size_t)s0 * F4 + lane]);
        float4 x1 = __ldg(&xin[(size_t)s1 * F4 + lane]);
        float4 x2 = __ldg(&xin[(size_t)s2 * F4 + lane]);
        float4 x3 = __ldg(&xin[(size_t)s3 * F4 + lane]);
        acc.x += fmaxf(fmaf(e0, w.x, x0.x) + bb.x, 0.f);
        acc.y += fmaxf(fmaf(e0, w.y, x0.y) + bb.y, 0.f);
        acc.z += fmaxf(fmaf(e0, w.z, x0.z) + bb.z, 0.f);
        acc.w += fmaxf(fmaf(e0, w.w, x0.w) + bb.w, 0.f);
        acc.x += fmaxf(fmaf(e1, w.x, x1.x) + bb.x, 0.f);
        acc.y += fmaxf(fmaf(e1, w.y, x1.y) + bb.y, 0.f);
        acc.z += fmaxf(fmaf(e1, w.z, x1.z) + bb.z, 0.f);
        acc.w += fmaxf(fmaf(e1, w.w, x1.w) + bb.w, 0.f);
        acc.x += fmaxf(fmaf(e2, w.x, x2.x) + bb.x, 0.f);
        acc.y += fmaxf(fmaf(e2, w.y, x2.y) + bb.y, 0.f);
        acc.z += fmaxf(fmaf(e2, w.z, x2.z) + bb.z, 0.f);
        acc.w += fmaxf(fmaf(e2, w.w, x2.w) + bb.w, 0.f);
        acc.x += fmaxf(fmaf(e3, w.x, x3.x) + bb.x, 0.f);
        acc.y += fmaxf(fmaf(e3, w.y, x3.y) + bb.y, 0.f);
        acc.z += fmaxf(fmaf(e3, w.z, x3.z) + bb.z, 0.f);
        acc.w += fmaxf(fmaf(e3, w.w, x3.w) + bb.w, 0.f);
    }
    for (; p < end; p++) {
        int   s  = g_perm_src[p];
        float ea = g_perm_ea[p];
        float4 xj = __ldg(&xin[(size_t)s * F4 + lane]);
        acc.x += fmaxf(fmaf(ea, w.x, xj.x) + bb.x, 0.f);
        acc.y += fmaxf(fmaf(ea, w.y, xj.y) + bb.y, 0.f);
        acc.z += fmaxf(fmaf(ea, w.z, xj.z) + bb.z, 0.f);
        acc.w += fmaxf(fmaf(ea, w.w, xj.w) + bb.w, 0.f);
    }
    float epv = 1.f + __ldg(eps_p);
    float4 xi = __ldg(&xin[(size_t)warp * F4 + lane]);
    float4 r;
    r.x = fmaf(epv, xi.x, acc.x);
    r.y = fmaf(epv, xi.y, acc.y);
    r.z = fmaf(epv, xi.z, acc.z);
    r.w = fmaf(epv, xi.w, acc.w);
    out[(size_t)warp * F4 + lane] = r;
}

// ---------------- tf32 helpers ----------------
__device__ __forceinline__ uint32_t f2tf32(float x) {
    uint32_t r;
    asm("cvt.rna.tf32.f32 %0, %1;" : "=r"(r) : "f"(x));
    return r;
}
__device__ __forceinline__ void split_tf32(float x, uint32_t& hi, uint32_t& lo) {
    hi = f2tf32(x);
    lo = f2tf32(x - __uint_as_float(hi));
}
__device__ __forceinline__ void mma_tf32(float* d, const uint32_t* a, const uint32_t* b) {
    asm volatile(
        "mma.sync.aligned.m16n8k8.row.col.f32.tf32.tf32.f32 "
        "{%0,%1,%2,%3}, {%4,%5,%6,%7}, {%8,%9}, {%0,%1,%2,%3};"
        : "+f"(d[0]), "+f"(d[1]), "+f"(d[2]), "+f"(d[3])
        : "r"(a[0]), "r"(a[1]), "r"(a[2]), "r"(a[3]), "r"(b[0]), "r"(b[1]));
}

// ---------------- tf32 tensor-core fused MLP (+ optional fused classifier) ----------------
#define TM   64
#define SLDK 132   // As[m][k] row stride (conflict-free)
#define SLDB 136   // Bs[k][n] row stride
#define LSLD 44
#define SMEM_MLP ((TM * SLDK + 128 * SLDB) * 4)
// cls scratch lives inside the Bs region after stage 2:
//   Ws (Wl compact, 128*40=5120 fl) at Bs+0
//   Ls (64*44=2816 fl)              at Bs+6144
//   bls (40 fl)                     at Bs+9088

template <bool FUSE_CLS>
__global__ void __launch_bounds__(256, 2) mlp_kernel(
    const float* __restrict__ In,
    const float* __restrict__ W1, const float* __restrict__ b1,
    const float* __restrict__ W2, const float* __restrict__ b2,
    float* __restrict__ Out, int n,
    const float* __restrict__ Wl, const float* __restrict__ bl,
    float* __restrict__ cls_out)
{
    extern __shared__ float sm[];
    float* As = sm;                // [TM m][128 k] row-major
    float* Bs = sm + TM * SLDK;    // [128 k][128 n]

    const int t    = threadIdx.x;
    const int lane = t & 31;
    const int wid  = t >> 5;
    const int wm   = wid & 1;
    const int wn   = wid >> 1;
    const int m0   = blockIdx.x * TM;
    const int lq   = lane & 3;
    const int lg   = lane >> 2;

    // Load In tile row-major
    #pragma unroll
    for (int r = 0; r < 8; r++) {
        int idx = t + r * 256;
        int m   = idx >> 5;
        int k4  = (idx & 31) * 4;
        float4 v = make_float4(0.f, 0.f, 0.f, 0.f);
        if (m0 + m < n) v = *(const float4*)(In + (size_t)(m0 + m) * F + k4);
        *(float4*)(As + m * SLDK + k4) = v;
    }
    // Load W1 into Bs
    #pragma unroll
    for (int r = 0; r < 16; r++) {
        int idx = t + r * 256;
        int k   = idx >> 5;
        int c4  = (idx & 31) * 4;
        *(float4*)(Bs + k * SLDB + c4) = *(const float4*)(W1 + k * F + c4);
    }
    __syncthreads();

    float acc[2][4][4];
    #pragma unroll
    for (int i = 0; i < 2; i++)
        #pragma unroll
        for (int j = 0; j < 4; j++)
            #pragma unroll
            for (int c = 0; c < 4; c++) acc[i][j][c] = 0.f;

    // ---- stage 1: T = In @ W1 ----
    #pragma unroll 4
    for (int ks = 0; ks < 128; ks += 8) {
        uint32_t ahi[2][4], alo[2][4], bhi[4][2], blo[4][2];
        #pragma unroll
        for (int mt = 0; mt < 2; mt++) {
            int mb = wm * 32 + mt * 16 + lg;
            const float* ap = As + mb * SLDK + ks + lq;
            split_tf32(ap[0],            ahi[mt][0], alo[mt][0]);
            split_tf32(ap[8 * SLDK],     ahi[mt][1], alo[mt][1]);
            split_tf32(ap[4],            ahi[mt][2], alo[mt][2]);
            split_tf32(ap[8 * SLDK + 4], ahi[mt][3], alo[mt][3]);
        }
        #pragma unroll
        for (int nt = 0; nt < 4; nt++) {
            int nb = wn * 32 + nt * 8 + lg;
            const float* bp = Bs + (ks + lq) * SLDB + nb;
            split_tf32(bp[0],        bhi[nt][0], blo[nt][0]);
            split_tf32(bp[4 * SLDB], bhi[nt][1], blo[nt][1]);
        }
        #pragma unroll
        for (int mt = 0; mt < 2; mt++)
            #pragma unroll
            for (int nt = 0; nt < 4; nt++) {
                mma_tf32(acc[mt][nt], ahi[mt], bhi[nt]);
                mma_tf32(acc[mt][nt], ahi[mt], blo[nt]);
                mma_tf32(acc[mt][nt], alo[mt], bhi[nt]);
            }
    }
    __syncthreads();

    // epilogue 1: T = relu(acc + b1) stored into As[m][hidden]
    #pragma unroll
    for (int mt = 0; mt < 2; mt++) {
        int r0 = wm * 32 + mt * 16 + lg;
        #pragma unroll
        for (int nt = 0; nt < 4; nt++) {
            int c = wn * 32 + nt * 8 + 2 * lq;
            float ba = __ldg(b1 + c), bb = __ldg(b1 + c + 1);
            float2 v0, v1;
            v0.x = fmaxf(acc[mt][nt][0] + ba, 0.f);
            v0.y = fmaxf(acc[mt][nt][1] + bb, 0.f);
            v1.x = fmaxf(acc[mt][nt][2] + ba, 0.f);
            v1.y = fmaxf(acc[mt][nt][3] + bb, 0.f);
            *(float2*)(As + r0 * SLDK + c)       = v0;
            *(float2*)(As + (r0 + 8) * SLDK + c) = v1;
            acc[mt][nt][0] = 0.f; acc[mt][nt][1] = 0.f;
            acc[mt][nt][2] = 0.f; acc[mt][nt][3] = 0.f;
        }
    }
    // Load W2 into Bs
    #pragma unroll
    for (int r = 0; r < 16; r++) {
        int idx = t + r * 256;
        int k   = idx >> 5;
        int c4  = (idx & 31) * 4;
        *(float4*)(Bs + k * SLDB + c4) = *(const float4*)(W2 + k * F + c4);
    }
    __syncthreads();

    // ---- stage 2: H = relu(T @ W2 + b2) ----
    #pragma unroll 4
    for (int ks = 0; ks < 128; ks += 8) {
        uint32_t ahi[2][4], alo[2][4], bhi[4][2], blo[4][2];
        #pragma unroll
        for (int mt = 0; mt < 2; mt++) {
            int mb = wm * 32 + mt * 16 + lg;
            const float* ap = As + mb * SLDK + ks + lq;
            split_tf32(ap[0],            ahi[mt][0], alo[mt][0]);
            split_tf32(ap[8 * SLDK],     ahi[mt][1], alo[mt][1]);
            split_tf32(ap[4],            ahi[mt][2], alo[mt][2]);
            split_tf32(ap[8 * SLDK + 4], ahi[mt][3], alo[mt][3]);
        }
        #pragma unroll
        for (int nt = 0; nt < 4; nt++) {
            int nb = wn * 32 + nt * 8 + lg;
            const float* bp = Bs + (ks + lq) * SLDB + nb;
            split_tf32(bp[0],        bhi[nt][0], blo[nt][0]);
            split_tf32(bp[4 * SLDB], bhi[nt][1], blo[nt][1]);
        }
        #pragma unroll
        for (int mt = 0; mt < 2; mt++)
            #pragma unroll
            for (int nt = 0; nt < 4; nt++) {
                mma_tf32(acc[mt][nt], ahi[mt], bhi[nt]);
                mma_tf32(acc[mt][nt], ahi[mt], blo[nt]);
                mma_tf32(acc[mt][nt], alo[mt], bhi[nt]);
            }
    }

    if (!FUSE_CLS) {
        // epilogue 2: write H to gmem
        #pragma unroll
        for (int mt = 0; mt < 2; mt++) {
            int r0 = m0 + wm * 32 + mt * 16 + lg;
            #pragma unroll
            for (int nt = 0; nt < 4; nt++) {
                int c = wn * 32 + nt * 8 + 2 * lq;
                float ba = __ldg(b2 + c), bb = __ldg(b2 + c + 1);
                if (r0 < n) {
                    float2 v;
                    v.x = fmaxf(acc[mt][nt][0] + ba, 0.f);
                    v.y = fmaxf(acc[mt][nt][1] + bb, 0.f);
                    *(float2*)(Out + (size_t)r0 * F + c) = v;
                }
                if (r0 + 8 < n) {
                    float2 v;
                    v.x = fmaxf(acc[mt][nt][2] + ba, 0.f);
                    v.y = fmaxf(acc[mt][nt][3] + bb, 0.f);
                    *(float2*)(Out + (size_t)(r0 + 8) * F + c) = v;
                }
            }
        }
    } else {
        // epilogue 2 (fused): H -> As[m][k], then classifier + log_softmax in-block
        __syncthreads();   // all warps done reading As (T)
        #pragma unroll
        for (int mt = 0; mt < 2; mt++) {
            int r0 = wm * 32 + mt * 16 + lg;
            #pragma unroll
            for (int nt = 0; nt < 4; nt++) {
                int c = wn * 32 + nt * 8 + 2 * lq;
                float ba = __ldg(b2 + c), bb = __ldg(b2 + c + 1);
                float2 v0, v1;
                v0.x = fmaxf(acc[mt][nt][0] + ba, 0.f);
                v0.y = fmaxf(acc[mt][nt][1] + bb, 0.f);
                v1.x = fmaxf(acc[mt][nt][2] + ba, 0.f);
                v1.y = fmaxf(acc[mt][nt][3] + bb, 0.f);
                *(float2*)(As + r0 * SLDK + c)       = v0;
                *(float2*)(As + (r0 + 8) * SLDK + c) = v1;
            }
        }
        // stage Wl (compact 128x40), bl into the dead Bs region
        float* Ws  = Bs;
        float* Ls  = Bs + 6144;
        float* bls = Bs + 9088;
        #pragma unroll
        for (int r = 0; r < 5; r++) {
            int idx = t + r * 256;
            ((float4*)Ws)[idx] = ((const float4*)Wl)[idx];
        }
        if (t < NCLS) bls[t] = bl[t];
        __syncthreads();

        if (wid < 4) {
            const int mb = wid * 16;
            float a5[5][4];
            #pragma unroll
            for (int j = 0; j < 5; j++)
                #pragma unroll
                for (int c = 0; c < 4; c++) a5[j][c] = 0.f;

            #pragma unroll 4
            for (int ks = 0; ks < 128; ks += 8) {
                uint32_t ahi[4], alo[4], bhi[5][2], blo[5][2];
                const float* ap = As + (mb + lg) * SLDK + ks + lq;
                split_tf32(ap[0],            ahi[0], alo[0]);
                split_tf32(ap[8 * SLDK],     ahi[1], alo[1]);
                split_tf32(ap[4],            ahi[2], alo[2]);
                split_tf32(ap[8 * SLDK + 4], ahi[3], alo[3]);
                #pragma unroll
                for (int nt = 0; nt < 5; nt++) {
                    const float* bp = Ws + (ks + lq) * NCLS + nt * 8 + lg;
                    split_tf32(bp[0],        bhi[nt][0], blo[nt][0]);
                    split_tf32(bp[4 * NCLS], bhi[nt][1], blo[nt][1]);
                }
                #pragma unroll
                for (int nt = 0; nt < 5; nt++) {
                    mma_tf32(a5[nt], ahi, bhi[nt]);
                    mma_tf32(a5[nt], ahi, blo[nt]);
                    mma_tf32(a5[nt], alo, bhi[nt]);
                }
            }
            #pragma unroll
            for (int nt = 0; nt < 5; nt++) {
                int c = nt * 8 + 2 * lq;
                float ba = bls[c], bb = bls[c + 1];
                Ls[(mb + lg) * LSLD + c]         = a5[nt][0] + ba;
                Ls[(mb + lg) * LSLD + c + 1]     = a5[nt][1] + bb;
                Ls[(mb + lg + 8) * LSLD + c]     = a5[nt][2] + ba;
                Ls[(mb + lg + 8) * LSLD + c + 1] = a5[nt][3] + bb;
            }
        }
        __syncthreads();

        if (t < 64 && m0 + t < n) {
            const float* row = Ls + t * LSLD;
            float vmax = row[0];
            #pragma unroll
            for (int i = 1; i < NCLS; i++) vmax = fmaxf(vmax, row[i]);
            float es = 0.f;
            #pragma unroll
            for (int i = 0; i < NCLS; i++) es += __expf(row[i] - vmax);
            float lse = vmax + __logf(es);
            float* op = cls_out + (size_t)(m0 + t) * NCLS;
            #pragma unroll
            for (int i = 0; i < NCLS; i++) op[i] = row[i] - lse;
        }
    }
}

// ---------------- host launch ----------------
extern "C" void kernel_launch(void* const* d_in, const int* in_sizes, int n_in,
                              void* d_out, int out_size)
{
    const float* x         = (const float*)d_in[0];
    const void*  edge_idx  = d_in[1];
    const float* edge_attr = (const float*)d_in[2];
    const float* eps1 = (const float*)d_in[3];
    const float* We1  = (const float*)d_in[4];
    const float* be1  = (const float*)d_in[5];
    const float* W11  = (const float*)d_in[6];
    const float* b11  = (const float*)d_in[7];
    const float* W12  = (const float*)d_in[8];
    const float* b12  = (const float*)d_in[9];
    const float* eps2 = (const float*)d_in[10];
    const float* We2  = (const float*)d_in[11];
    const float* be2  = (const float*)d_in[12];
    const float* W21  = (const float*)d_in[13];
    const float* b21  = (const float*)d_in[14];
    const float* W22  = (const float*)d_in[15];
    const float* b22  = (const float*)d_in[16];
    const float* Wl   = (const float*)d_in[17];
    const float* bl   = (const float*)d_in[18];
    float* out = (float*)d_out;

    const int N = in_sizes[0] / F;
    const int E = in_sizes[2];

    static float *buf_a = nullptr, *buf_b = nullptr;
    if (!buf_a) {
        cudaGetSymbolAddress((void**)&buf_a, g_buf_a);
        cudaGetSymbolAddress((void**)&buf_b, g_buf_b);
        cudaFuncSetAttribute(mlp_kernel<false>, cudaFuncAttributeMaxDynamicSharedMemorySize, SMEM_MLP);
        cudaFuncSetAttribute(mlp_kernel<true>,  cudaFuncAttributeMaxDynamicSharedMemorySize, SMEM_MLP);
    }

    const int TB = 256;
    int ebl = (E + TB - 1) / TB;
    int nbl = (N + TB) / TB;
    int wbl = (N * 32 + TB - 1) / TB;
    int mbl = (N + TM - 1) / TM;

    // CSR build (5 launches; agg1 is launch #6 for ncu -s 5 capture)
    detect_kernel<<<1, 256>>>((const unsigned int*)edge_idx);
    zero_counts_kernel<<<nbl, TB>>>(N);
    extract_hist_kernel<<<ebl, TB>>>(edge_idx, E);
    scan_kernel<<<1, 1024>>>(N);
    scatter_kernel<<<ebl, TB>>>(edge_attr, E);

    // conv1
    agg_kernel<<<wbl, TB>>>((const float4*)x, We1, be1, eps1, (float4*)buf_a, N);
    mlp_kernel<false><<<mbl, TB, SMEM_MLP>>>(buf_a, W11, b11, W12, b12, buf_b, N,
                                             nullptr, nullptr, nullptr);
    // conv2 + fused classifier/log_softmax
    agg_kernel<<<wbl, TB>>>((const float4*)buf_b, We2, be2, eps2, (float4*)buf_a, N);
    mlp_kernel<true><<<mbl, TB, SMEM_MLP>>>(buf_a, W21, b21, W22, b22, nullptr, N,
                                            Wl, bl, out);
}

// round 10
// speedup vs baseline: 1.9409x; 1.3223x over previous
#include <cuda_runtime.h>
#include <math_constants.h>
#include <stdint.h>

#define MAXN 100000
#define MAXE 1600000
#define F 128
#define F4 32
#define NCLS 40
#define NSB  128   // max scan blocks (MAXN/1024+1 = 99)

// ---------------- device scratch ----------------
__device__ int   g_is64;
__device__ int   g_src[MAXE];
__device__ int   g_dst[MAXE];
__device__ int   g_perm_src[MAXE];
__device__ float g_perm_ea[MAXE];
__device__ int   g_counts[MAXN + 1];
__device__ int   g_offsets[MAXN + 1];
__device__ int   g_cursor[MAXN];
__device__ int   g_bsum[NSB];
__device__ int   g_boff[NSB];
__device__ float g_buf_a[(size_t)MAXN * F];
__device__ float g_buf_b[(size_t)MAXN * F];

// ---------------- dtype detection ----------------
__global__ void detect_kernel(const unsigned int* __restrict__ ei) {
    __shared__ int any_nonzero;
    if (threadIdx.x == 0) any_nonzero = 0;
    __syncthreads();
    for (int i = threadIdx.x; i < 1024; i += blockDim.x) {
        if (ei[2 * i + 1] != 0u) any_nonzero = 1;
    }
    __syncthreads();
    if (threadIdx.x == 0) g_is64 = (any_nonzero == 0) ? 1 : 0;
}

__global__ void zero_counts_kernel(int n) {
    int i = blockIdx.x * blockDim.x + threadIdx.x;
    if (i <= n) g_counts[i] = 0;
}

// extract + histogram in one pass over E
__global__ void extract_hist_kernel(const void* __restrict__ ei, int E) {
    int e = blockIdx.x * blockDim.x + threadIdx.x;
    if (e >= E) return;
    int s, d;
    if (g_is64) {
        const long long* p = (const long long*)ei;
        s = (int)p[e];
        d = (int)p[(size_t)E + e];
    } else {
        const int* p = (const int*)ei;
        s = p[e];
        d = p[E + e];
    }
    g_src[e] = s;
    g_dst[e] = d;
    atomicAdd(&g_counts[d], 1);
}

// ---------------- 3-phase coalesced scan over counts[0..n] ----------------
// phase 1: per-block (1024-element) sums
__global__ void __launch_bounds__(1024) scan_sums_kernel(int n) {
    __shared__ int wsum[32];
    int i = blockIdx.x * 1024 + threadIdx.x;
    int v = (i <= n) ? g_counts[i] : 0;
    #pragma unroll
    for (int o = 16; o > 0; o >>= 1) v += __shfl_xor_sync(0xffffffffu, v, o);
    if ((threadIdx.x & 31) == 0) wsum[threadIdx.x >> 5] = v;
    __syncthreads();
    if (threadIdx.x < 32) {
        int s = wsum[threadIdx.x];
        #pragma unroll
        for (int o = 16; o > 0; o >>= 1) s += __shfl_xor_sync(0xffffffffu, s, o);
        if (threadIdx.x == 0) g_bsum[blockIdx.x] = s;
    }
}

// phase 2: exclusive scan over block sums (nb <= 128), single block
__global__ void scan_blocks_kernel(int nb) {
    __shared__ int sm[NSB];
    int t = threadIdx.x;
    int v = (t < nb) ? g_bsum[t] : 0;
    sm[t] = v;
    __syncthreads();
    #pragma unroll
    for (int o = 1; o < NSB; o <<= 1) {
        int y = (t >= o) ? sm[t - o] : 0;
        __syncthreads();
        sm[t] += y;
        __syncthreads();
    }
    if (t < nb) g_boff[t] = sm[t] - v;   // exclusive
}

// phase 3: block-local exclusive scan + block offset -> offsets/cursor
__global__ void __launch_bounds__(1024) scan_apply_kernel(int n) {
    __shared__ int wsum[32];
    int lane = threadIdx.x & 31;
    int wid  = threadIdx.x >> 5;
    int i = blockIdx.x * 1024 + threadIdx.x;
    int v = (i <= n) ? g_counts[i] : 0;
    int x = v;
    #pragma unroll
    for (int o = 1; o < 32; o <<= 1) {
        int y = __shfl_up_sync(0xffffffffu, x, o);
        if (lane >= o) x += y;
    }
    if (lane == 31) wsum[wid] = x;
    __syncthreads();
    if (wid == 0) {
        int s = wsum[lane];
        #pragma unroll
        for (int o = 1; o < 32; o <<= 1) {
            int y = __shfl_up_sync(0xffffffffu, s, o);
            if (lane >= o) s += y;
        }
        wsum[lane] = s;
    }
    __syncthreads();
    int excl = x - v + (wid > 0 ? wsum[wid - 1] : 0) + g_boff[blockIdx.x];
    if (i <= n) {
        g_offsets[i] = excl;
        if (i < n) g_cursor[i] = excl;
    }
}

__global__ void scatter_kernel(const float* __restrict__ edge_attr, int E) {
    int e = blockIdx.x * blockDim.x + threadIdx.x;
    if (e >= E) return;
    int d = g_dst[e];
    int pos = atomicAdd(&g_cursor[d], 1);
    g_perm_src[pos] = g_src[e];
    g_perm_ea[pos]  = edge_attr[e];
}

// ---------------- GINE aggregation: warp per node, unroll-4 for MLP ----------------
__global__ void __launch_bounds__(256) agg_kernel(
    const float4* __restrict__ xin, const float* __restrict__ We,
    const float* __restrict__ be, const float* __restrict__ eps_p,
    float4* __restrict__ out, int n)
{
    int warp = (blockIdx.x * blockDim.x + threadIdx.x) >> 5;
    int lane = threadIdx.x & 31;
    if (warp >= n) return;

    float4 w  = ((const float4*)We)[lane];
    float4 bb = ((const float4*)be)[lane];
    int beg = g_offsets[warp];
    int end = g_offsets[warp + 1];

    float4 acc = make_float4(0.f, 0.f, 0.f, 0.f);
    int p = beg;
    for (; p + 3 < end; p += 4) {
        int s0 = g_perm_src[p];
        int s1 = g_perm_src[p + 1];
        int s2 = g_perm_src[p + 2];
        int s3 = g_perm_src[p + 3];
        float e0 = g_perm_ea[p];
        float e1 = g_perm_ea[p + 1];
        float e2 = g_perm_ea[p + 2];
        float e3 = g_perm_ea[p + 3];
        float4 x0 = __ldg(&xin[(size_t)s0 * F4 + lane]);
        float4 x1 = __ldg(&xin[(size_t)s1 * F4 + lane]);
        float4 x2 = __ldg(&xin[(size_t)s2 * F4 + lane]);
        float4 x3 = __ldg(&xin[(size_t)s3 * F4 + lane]);
        acc.x += fmaxf(fmaf(e0, w.x, x0.x) + bb.x, 0.f);
        acc.y += fmaxf(fmaf(e0, w.y, x0.y) + bb.y, 0.f);
        acc.z += fmaxf(fmaf(e0, w.z, x0.z) + bb.z, 0.f);
        acc.w += fmaxf(fmaf(e0, w.w, x0.w) + bb.w, 0.f);
        acc.x += fmaxf(fmaf(e1, w.x, x1.x) + bb.x, 0.f);
        acc.y += fmaxf(fmaf(e1, w.y, x1.y) + bb.y, 0.f);
        acc.z += fmaxf(fmaf(e1, w.z, x1.z) + bb.z, 0.f);
        acc.w += fmaxf(fmaf(e1, w.w, x1.w) + bb.w, 0.f);
        acc.x += fmaxf(fmaf(e2, w.x, x2.x) + bb.x, 0.f);
        acc.y += fmaxf(fmaf(e2, w.y, x2.y) + bb.y, 0.f);
        acc.z += fmaxf(fmaf(e2, w.z, x2.z) + bb.z, 0.f);
        acc.w += fmaxf(fmaf(e2, w.w, x2.w) + bb.w, 0.f);
        acc.x += fmaxf(fmaf(e3, w.x, x3.x) + bb.x, 0.f);
        acc.y += fmaxf(fmaf(e3, w.y, x3.y) + bb.y, 0.f);
        acc.z += fmaxf(fmaf(e3, w.z, x3.z) + bb.z, 0.f);
        acc.w += fmaxf(fmaf(e3, w.w, x3.w) + bb.w, 0.f);
    }
    for (; p < end; p++) {
        int   s  = g_perm_src[p];
        float ea = g_perm_ea[p];
        float4 xj = __ldg(&xin[(size_t)s * F4 + lane]);
        acc.x += fmaxf(fmaf(ea, w.x, xj.x) + bb.x, 0.f);
        acc.y += fmaxf(fmaf(ea, w.y, xj.y) + bb.y, 0.f);
        acc.z += fmaxf(fmaf(ea, w.z, xj.z) + bb.z, 0.f);
        acc.w += fmaxf(fmaf(ea, w.w, xj.w) + bb.w, 0.f);
    }
    float epv = 1.f + __ldg(eps_p);
    float4 xi = __ldg(&xin[(size_t)warp * F4 + lane]);
    float4 r;
    r.x = fmaf(epv, xi.x, acc.x);
    r.y = fmaf(epv, xi.y, acc.y);
    r.z = fmaf(epv, xi.z, acc.z);
    r.w = fmaf(epv, xi.w, acc.w);
    out[(size_t)warp * F4 + lane] = r;
}

// ---------------- tf32 helpers ----------------
__device__ __forceinline__ uint32_t f2tf32(float x) {
    uint32_t r;
    asm("cvt.rna.tf32.f32 %0, %1;" : "=r"(r) : "f"(x));
    return r;
}
__device__ __forceinline__ void split_tf32(float x, uint32_t& hi, uint32_t& lo) {
    hi = f2tf32(x);
    lo = f2tf32(x - __uint_as_float(hi));
}
__device__ __forceinline__ void mma_tf32(float* d, const uint32_t* a, const uint32_t* b) {
    asm volatile(
        "mma.sync.aligned.m16n8k8.row.col.f32.tf32.tf32.f32 "
        "{%0,%1,%2,%3}, {%4,%5,%6,%7}, {%8,%9}, {%0,%1,%2,%3};"
        : "+f"(d[0]), "+f"(d[1]), "+f"(d[2]), "+f"(d[3])
        : "r"(a[0]), "r"(a[1]), "r"(a[2]), "r"(a[3]), "r"(b[0]), "r"(b[1]));
}

// ---------------- tf32 tensor-core fused MLP (+ optional fused classifier) ----------------
#define TM   64
#define SLDK 132   // As[m][k] row stride (conflict-free)
#define SLDB 136   // Bs[k][n] row stride
#define LSLD 44
#define SMEM_MLP ((TM * SLDK + 128 * SLDB) * 4)

template <bool FUSE_CLS>
__global__ void __launch_bounds__(256, 2) mlp_kernel(
    const float* __restrict__ In,
    const float* __restrict__ W1, const float* __restrict__ b1,
    const float* __restrict__ W2, const float* __restrict__ b2,
    float* __restrict__ Out, int n,
    const float* __restrict__ Wl, const float* __restrict__ bl,
    float* __restrict__ cls_out)
{
    extern __shared__ float sm[];
    float* As = sm;                // [TM m][128 k] row-major
    float* Bs = sm + TM * SLDK;    // [128 k][128 n]

    const int t    = threadIdx.x;
    const int lane = t & 31;
    const int wid  = t >> 5;
    const int wm   = wid & 1;
    const int wn   = wid >> 1;
    const int m0   = blockIdx.x * TM;
    const int lq   = lane & 3;
    const int lg   = lane >> 2;

    // Load In tile row-major
    #pragma unroll
    for (int r = 0; r < 8; r++) {
        int idx = t + r * 256;
        int m   = idx >> 5;
        int k4  = (idx & 31) * 4;
        float4 v = make_float4(0.f, 0.f, 0.f, 0.f);
        if (m0 + m < n) v = *(const float4*)(In + (size_t)(m0 + m) * F + k4);
        *(float4*)(As + m * SLDK + k4) = v;
    }
    // Load W1 into Bs
    #pragma unroll
    for (int r = 0; r < 16; r++) {
        int idx = t + r * 256;
        int k   = idx >> 5;
        int c4  = (idx & 31) * 4;
        *(float4*)(Bs + k * SLDB + c4) = *(const float4*)(W1 + k * F + c4);
    }
    __syncthreads();

    float acc[2][4][4];
    #pragma unroll
    for (int i = 0; i < 2; i++)
        #pragma unroll
        for (int j = 0; j < 4; j++)
            #pragma unroll
            for (int c = 0; c < 4; c++) acc[i][j][c] = 0.f;

    // ---- stage 1: T = In @ W1 ----
    #pragma unroll 4
    for (int ks = 0; ks < 128; ks += 8) {
        uint32_t ahi[2][4], alo[2][4], bhi[4][2], blo[4][2];
        #pragma unroll
        for (int mt = 0; mt < 2; mt++) {
            int mb = wm * 32 + mt * 16 + lg;
            const float* ap = As + mb * SLDK + ks + lq;
            split_tf32(ap[0],            ahi[mt][0], alo[mt][0]);
            split_tf32(ap[8 * SLDK],     ahi[mt][1], alo[mt][1]);
            split_tf32(ap[4],            ahi[mt][2], alo[mt][2]);
            split_tf32(ap[8 * SLDK + 4], ahi[mt][3], alo[mt][3]);
        }
        #pragma unroll
        for (int nt = 0; nt < 4; nt++) {
            int nb = wn * 32 + nt * 8 + lg;
            const float* bp = Bs + (ks + lq) * SLDB + nb;
            split_tf32(bp[0],        bhi[nt][0], blo[nt][0]);
            split_tf32(bp[4 * SLDB], bhi[nt][1], blo[nt][1]);
        }
        #pragma unroll
        for (int mt = 0; mt < 2; mt++)
            #pragma unroll
            for (int nt = 0; nt < 4; nt++) {
                mma_tf32(acc[mt][nt], ahi[mt], bhi[nt]);
                mma_tf32(acc[mt][nt], ahi[mt], blo[nt]);
                mma_tf32(acc[mt][nt], alo[mt], bhi[nt]);
            }
    }
    __syncthreads();

    // epilogue 1: T = relu(acc + b1) stored into As[m][hidden]
    #pragma unroll
    for (int mt = 0; mt < 2; mt++) {
        int r0 = wm * 32 + mt * 16 + lg;
        #pragma unroll
        for (int nt = 0; nt < 4; nt++) {
            int c = wn * 32 + nt * 8 + 2 * lq;
            float ba = __ldg(b1 + c), bb = __ldg(b1 + c + 1);
            float2 v0, v1;
            v0.x = fmaxf(acc[mt][nt][0] + ba, 0.f);
            v0.y = fmaxf(acc[mt][nt][1] + bb, 0.f);
            v1.x = fmaxf(acc[mt][nt][2] + ba, 0.f);
            v1.y = fmaxf(acc[mt][nt][3] + bb, 0.f);
            *(float2*)(As + r0 * SLDK + c)       = v0;
            *(float2*)(As + (r0 + 8) * SLDK + c) = v1;
            acc[mt][nt][0] = 0.f; acc[mt][nt][1] = 0.f;
            acc[mt][nt][2] = 0.f; acc[mt][nt][3] = 0.f;
        }
    }
    // Load W2 into Bs
    #pragma unroll
    for (int r = 0; r < 16; r++) {
        int idx = t + r * 256;
        int k   = idx >> 5;
        int c4  = (idx & 31) * 4;
        *(float4*)(Bs + k * SLDB + c4) = *(const float4*)(W2 + k * F + c4);
    }
    __syncthreads();

    // ---- stage 2: H = relu(T @ W2 + b2) ----
    #pragma unroll 4
    for (int ks = 0; ks < 128; ks += 8) {
        uint32_t ahi[2][4], alo[2][4], bhi[4][2], blo[4][2];
        #pragma unroll
        for (int mt = 0; mt < 2; mt++) {
            int mb = wm * 32 + mt * 16 + lg;
            const float* ap = As + mb * SLDK + ks + lq;
            split_tf32(ap[0],            ahi[mt][0], alo[mt][0]);
            split_tf32(ap[8 * SLDK],     ahi[mt][1], alo[mt][1]);
            split_tf32(ap[4],            ahi[mt][2], alo[mt][2]);
            split_tf32(ap[8 * SLDK + 4], ahi[mt][3], alo[mt][3]);
        }
        #pragma unroll
        for (int nt = 0; nt < 4; nt++) {
            int nb = wn * 32 + nt * 8 + lg;
            const float* bp = Bs + (ks + lq) * SLDB + nb;
            split_tf32(bp[0],        bhi[nt][0], blo[nt][0]);
            split_tf32(bp[4 * SLDB], bhi[nt][1], blo[nt][1]);
        }
        #pragma unroll
        for (int mt = 0; mt < 2; mt++)
            #pragma unroll
            for (int nt = 0; nt < 4; nt++) {
                mma_tf32(acc[mt][nt], ahi[mt], bhi[nt]);
                mma_tf32(acc[mt][nt], ahi[mt], blo[nt]);
                mma_tf32(acc[mt][nt], alo[mt], bhi[nt]);
            }
    }

    if (!FUSE_CLS) {
        // epilogue 2: write H to gmem
        #pragma unroll
        for (int mt = 0; mt < 2; mt++) {
            int r0 = m0 + wm * 32 + mt * 16 + lg;
            #pragma unroll
            for (int nt = 0; nt < 4; nt++) {
                int c = wn * 32 + nt * 8 + 2 * lq;
                float ba = __ldg(b2 + c), bb = __ldg(b2 + c + 1);
                if (r0 < n) {
                    float2 v;
                    v.x = fmaxf(acc[mt][nt][0] + ba, 0.f);
                    v.y = fmaxf(acc[mt][nt][1] + bb, 0.f);
                    *(float2*)(Out + (size_t)r0 * F + c) = v;
                }
                if (r0 + 8 < n) {
                    float2 v;
                    v.x = fmaxf(acc[mt][nt][2] + ba, 0.f);
                    v.y = fmaxf(acc[mt][nt][3] + bb, 0.f);
                    *(float2*)(Out + (size_t)(r0 + 8) * F + c) = v;
                }
            }
        }
    } else {
        // epilogue 2 (fused): H -> As[m][k], then classifier + log_softmax in-block
        __syncthreads();   // all warps done reading As (T)
        #pragma unroll
        for (int mt = 0; mt < 2; mt++) {
            int r0 = wm * 32 + mt * 16 + lg;
            #pragma unroll
            for (int nt = 0; nt < 4; nt++) {
                int c = wn * 32 + nt * 8 + 2 * lq;
                float ba = __ldg(b2 + c), bb = __ldg(b2 + c + 1);
                float2 v0, v1;
                v0.x = fmaxf(acc[mt][nt][0] + ba, 0.f);
                v0.y = fmaxf(acc[mt][nt][1] + bb, 0.f);
                v1.x = fmaxf(acc[mt][nt][2] + ba, 0.f);
                v1.y = fmaxf(acc[mt][nt][3] + bb, 0.f);
                *(float2*)(As + r0 * SLDK + c)       = v0;
                *(float2*)(As + (r0 + 8) * SLDK + c) = v1;
            }
        }
        // stage Wl (compact 128x40), bl into the dead Bs region
        float* Ws  = Bs;
        float* Ls  = Bs + 6144;
        float* bls = Bs + 9088;
        #pragma unroll
        for (int r = 0; r < 5; r++) {
            int idx = t + r * 256;
            ((float4*)Ws)[idx] = ((const float4*)Wl)[idx];
        }
        if (t < NCLS) bls[t] = bl[t];
        __syncthreads();

        if (wid < 4) {
            const int mb = wid * 16;
            float a5[5][4];
            #pragma unroll
            for (int j = 0; j < 5; j++)
                #pragma unroll
                for (int c = 0; c < 4; c++) a5[j][c] = 0.f;

            #pragma unroll 4
            for (int ks = 0; ks < 128; ks += 8) {
                uint32_t ahi[4], alo[4], bhi[5][2], blo[5][2];
                const float* ap = As + (mb + lg) * SLDK + ks + lq;
                split_tf32(ap[0],            ahi[0], alo[0]);
                split_tf32(ap[8 * SLDK],     ahi[1], alo[1]);
                split_tf32(ap[4],            ahi[2], alo[2]);
                split_tf32(ap[8 * SLDK + 4], ahi[3], alo[3]);
                #pragma unroll
                for (int nt = 0; nt < 5; nt++) {
                    const float* bp = Ws + (ks + lq) * NCLS + nt * 8 + lg;
                    split_tf32(bp[0],        bhi[nt][0], blo[nt][0]);
                    split_tf32(bp[4 * NCLS], bhi[nt][1], blo[nt][1]);
                }
                #pragma unroll
                for (int nt = 0; nt < 5; nt++) {
                    mma_tf32(a5[nt], ahi, bhi[nt]);
                    mma_tf32(a5[nt], ahi, blo[nt]);
                    mma_tf32(a5[nt], alo, bhi[nt]);
                }
            }
            #pragma unroll
            for (int nt = 0; nt < 5; nt++) {
                int c = nt * 8 + 2 * lq;
                float ba = bls[c], bb = bls[c + 1];
                Ls[(mb + lg) * LSLD + c]         = a5[nt][0] + ba;
                Ls[(mb + lg) * LSLD + c + 1]     = a5[nt][1] + bb;
                Ls[(mb + lg + 8) * LSLD + c]     = a5[nt][2] + ba;
                Ls[(mb + lg + 8) * LSLD + c + 1] = a5[nt][3] + bb;
            }
        }
        __syncthreads();

        if (t < 64 && m0 + t < n) {
            const float* row = Ls + t * LSLD;
            float vmax = row[0];
            #pragma unroll
            for (int i = 1; i < NCLS; i++) vmax = fmaxf(vmax, row[i]);
            float es = 0.f;
            #pragma unroll
            for (int i = 0; i < NCLS; i++) es += __expf(row[i] - vmax);
            float lse = vmax + __logf(es);
            float* op = cls_out + (size_t)(m0 + t) * NCLS;
            #pragma unroll
            for (int i = 0; i < NCLS; i++) op[i] = row[i] - lse;
        }
    }
}

// ---------------- host launch ----------------
extern "C" void kernel_launch(void* const* d_in, const int* in_sizes, int n_in,
                              void* d_out, int out_size)
{
    const float* x         = (const float*)d_in[0];
    const void*  edge_idx  = d_in[1];
    const float* edge_attr = (const float*)d_in[2];
    const float* eps1 = (const float*)d_in[3];
    const float* We1  = (const float*)d_in[4];
    const float* be1  = (const float*)d_in[5];
    const float* W11  = (const float*)d_in[6];
    const float* b11  = (const float*)d_in[7];
    const float* W12  = (const float*)d_in[8];
    const float* b12  = (const float*)d_in[9];
    const float* eps2 = (const float*)d_in[10];
    const float* We2  = (const float*)d_in[11];
    const float* be2  = (const float*)d_in[12];
    const float* W21  = (const float*)d_in[13];
    const float* b21  = (const float*)d_in[14];
    const float* W22  = (const float*)d_in[15];
    const float* b22  = (const float*)d_in[16];
    const float* Wl   = (const float*)d_in[17];
    const float* bl   = (const float*)d_in[18];
    float* out = (float*)d_out;

    const int N = in_sizes[0] / F;
    const int E = in_sizes[2];

    static float *buf_a = nullptr, *buf_b = nullptr;
    if (!buf_a) {
        cudaGetSymbolAddress((void**)&buf_a, g_buf_a);
        cudaGetSymbolAddress((void**)&buf_b, g_buf_b);
        cudaFuncSetAttribute(mlp_kernel<false>, cudaFuncAttributeMaxDynamicSharedMemorySize, SMEM_MLP);
        cudaFuncSetAttribute(mlp_kernel<true>,  cudaFuncAttributeMaxDynamicSharedMemorySize, SMEM_MLP);
    }

    const int TB = 256;
    int ebl = (E + TB - 1) / TB;
    int nbl = (N + TB) / TB;
    int wbl = (N * 32 + TB - 1) / TB;
    int mbl = (N + TM - 1) / TM;
    int sbl = (N + 1 + 1023) / 1024;   // scan blocks (<= NSB)

    // CSR build
    detect_kernel<<<1, 256>>>((const unsigned int*)edge_idx);
    zero_counts_kernel<<<nbl, TB>>>(N);
    extract_hist_kernel<<<ebl, TB>>>(edge_idx, E);
    scan_sums_kernel<<<sbl, 1024>>>(N);
    scan_blocks_kernel<<<1, NSB>>>(sbl);
    scan_apply_kernel<<<sbl, 1024>>>(N);
    scatter_kernel<<<ebl, TB>>>(edge_attr, E);

    // conv1
    agg_kernel<<<wbl, TB>>>((const float4*)x, We1, be1, eps1, (float4*)buf_a, N);
    mlp_kernel<false><<<mbl, TB, SMEM_MLP>>>(buf_a, W11, b11, W12, b12, buf_b, N,
                                             nullptr, nullptr, nullptr);
    // conv2 + fused classifier/log_softmax
    agg_kernel<<<wbl, TB>>>((const float4*)buf_b, We2, be2, eps2, (float4*)buf_a, N);
    mlp_kernel<true><<<mbl, TB, SMEM_MLP>>>(buf_a, W21, b21, W22, b22, nullptr, N,
                                            Wl, bl, out);
}